// round 15
// baseline (speedup 1.0000x reference)
#include <cuda_runtime.h>
#include <math.h>
#include <stdint.h>

#define HW 4096
#define WW 64
#define HH 64

typedef unsigned long long u64;

// ---------------- packed f32x2 helpers ----------------
__device__ __forceinline__ u64 pk(float v) {
    u64 r; asm("mov.b64 %0, {%1, %1};" : "=l"(r) : "f"(v)); return r;
}
__device__ __forceinline__ u64 pk2(float a, float b) {
    u64 r; asm("mov.b64 %0, {%1, %2};" : "=l"(r) : "f"(a), "f"(b)); return r;
}
__device__ __forceinline__ void fma2(u64& d, u64 a, u64 b) {
    asm("fma.rn.f32x2 %0, %1, %2, %0;" : "+l"(d) : "l"(a), "l"(b));
}
__device__ __forceinline__ float2 up2(u64 v) {
    float2 f; asm("mov.b64 {%0, %1}, %2;" : "=f"(f.x), "=f"(f.y) : "l"(v)); return f;
}

// ---------------- cp.async helpers ----------------
__device__ __forceinline__ void cpa16(uint32_t dst, const void* src, bool v) {
    int sz = v ? 16 : 0;
    asm volatile("cp.async.ca.shared.global [%0], [%1], 16, %2;" :: "r"(dst), "l"(src), "r"(sz));
}
__device__ __forceinline__ void cp_commit() { asm volatile("cp.async.commit_group;"); }
template<int N> __device__ __forceinline__ void cp_wait() {
    asm volatile("cp.async.wait_group %0;" :: "n"(N));
}

// ---------------- bf16 helpers (sm_80+ baseline PTX) ----------------
__device__ __forceinline__ uint32_t bfpack(float e0, float e1) {
    uint32_t r; asm("cvt.rn.bf16x2.f32 %0, %1, %2;" : "=r"(r) : "f"(e1), "f"(e0));
    return r;
}
__device__ __forceinline__ float bf_hi(float x) {
    uint32_t u; asm("cvt.rn.bf16x2.f32 %0, %1, %1;" : "=r"(u) : "f"(x));
    return __uint_as_float(u << 16);
}
__device__ __forceinline__ void mma_bf16(float* d, const uint32_t* a,
                                         uint32_t b0, uint32_t b1) {
    asm volatile(
        "mma.sync.aligned.m16n8k16.row.col.f32.bf16.bf16.f32 "
        "{%0,%1,%2,%3}, {%4,%5,%6,%7}, {%8,%9}, {%0,%1,%2,%3};"
        : "+f"(d[0]), "+f"(d[1]), "+f"(d[2]), "+f"(d[3])
        : "r"(a[0]), "r"(a[1]), "r"(a[2]), "r"(a[3]), "r"(b0), "r"(b1));
}

// ---------------- device scratch ----------------
__device__ float    g_emb [12L*96*HW];       // NCHW
__device__ float    g_qkv [12L*HW*288];      // channel-last (attn)
__device__ uint32_t g_q32h[12L*3*HW*16];     // q tile bf16-pairs hi
__device__ uint32_t g_q32l[12L*3*HW*16];
__device__ uint32_t g_k32h[12L*3*HW*16];
__device__ uint32_t g_k32l[12L*3*HW*16];
__device__ float    g_aq32[12L*3*HW*32];     // oc1(q) out, fp32 tile-32
__device__ float    g_ak32[12L*3*HW*32];
__device__ uint32_t g_off1h[24L*3*HW*16];    // lrelu(aq+ak+b), bf16-pairs
__device__ uint32_t g_off1l[24L*3*HW*16];
__device__ uint32_t g_off2h[24L*3*HW*16];
__device__ uint32_t g_off2l[24L*3*HW*16];
__device__ float    g_om  [24L*HW*216];      // channel-last (attn)
__device__ float    g_wall[24L*HW];
__device__ float    g_vall[24L*HW*96];
__device__ float    g_f   [12L*96*HW];       // NCHW
__device__ float    g_cfwt [64*9*96];
__device__ float    g_qkvwt[96*288];
__device__ float    g_qkvb [288];
__device__ uint32_t g_oc1qh[96*432];         // bf16-pair weights, [cout][tap*48+cinp]
__device__ uint32_t g_oc1ql[96*432];
__device__ uint32_t g_oc1kh[96*432];
__device__ uint32_t g_oc1kl[96*432];
__device__ uint32_t g_oc2h [96*432];
__device__ uint32_t g_oc2l [96*432];
__device__ uint32_t g_omwth[216*432];
__device__ uint32_t g_omwtl[216*432];
__device__ float    g_clwt [96*9*64];
__device__ float    g_zero [256];

// ---------------- single prep kernel ----------------
__global__ void prep_all(const float* __restrict__ cf_w,
                         const float* __restrict__ wq, const float* __restrict__ wk,
                         const float* __restrict__ wv,
                         const float* __restrict__ bq, const float* __restrict__ bk,
                         const float* __restrict__ bv,
                         const float* __restrict__ oc1_w, const float* __restrict__ oc2_w,
                         const float* __restrict__ om_w,  const float* __restrict__ cl_w)
{
    int i = blockIdx.x*256 + threadIdx.x;
    if (i < 55296) { int d = i/576, k = i%576; g_cfwt[k*96+d] = cf_w[i]; return; }
    i -= 55296;
    if (i < 9216) {
        int d = i/96, c = i%96;
        g_qkvwt[c*288 + d]       = wq[i];
        g_qkvwt[c*288 + 96 + d]  = wk[i];
        g_qkvwt[c*288 + 192 + d] = wv[i];
        return;
    }
    i -= 9216;
    if (i < 96) { g_qkvb[i] = bq[i]; g_qkvb[96+i] = bk[i]; g_qkvb[192+i] = bv[i]; return; }
    i -= 96;
    if (i < 82944) {   // oc1: pairs over 192 cin
        int d = i/864, rem = i%864, cp = rem/9, tap = rem%9;
        int cin0 = 2*cp;
        float w0 = oc1_w[d*1728 + cin0*9 + tap];
        float w1 = oc1_w[d*1728 + (cin0+1)*9 + tap];
        float h0 = bf_hi(w0), h1 = bf_hi(w1);
        uint32_t hp = bfpack(h0, h1);
        uint32_t lp = bfpack(w0-h0, w1-h1);
        if (cin0 < 96) { int idx = d*432 + tap*48 + cp;      g_oc1qh[idx]=hp; g_oc1ql[idx]=lp; }
        else           { int idx = d*432 + tap*48 + (cp-48); g_oc1kh[idx]=hp; g_oc1kl[idx]=lp; }
        return;
    }
    i -= 82944;
    if (i < 41472) {   // oc2
        int d = i/432, rem = i%432, cp = rem/9, tap = rem%9;
        int cin0 = 2*cp;
        float w0 = oc2_w[d*864 + cin0*9 + tap];
        float w1 = oc2_w[d*864 + (cin0+1)*9 + tap];
        float h0 = bf_hi(w0), h1 = bf_hi(w1);
        int idx = d*432 + tap*48 + cp;
        g_oc2h[idx] = bfpack(h0, h1);
        g_oc2l[idx] = bfpack(w0-h0, w1-h1);
        return;
    }
    i -= 41472;
    if (i < 93312) {   // om
        int d = i/432, rem = i%432, cp = rem/9, tap = rem%9;
        int cin0 = 2*cp;
        float w0 = om_w[d*864 + cin0*9 + tap];
        float w1 = om_w[d*864 + (cin0+1)*9 + tap];
        float h0 = bf_hi(w0), h1 = bf_hi(w1);
        int idx = d*432 + tap*48 + cp;
        g_omwth[idx] = bfpack(h0, h1);
        g_omwtl[idx] = bfpack(w0-h0, w1-h1);
        return;
    }
    i -= 93312;
    if (i < 55296) { int d = i/864, k = i%864; g_clwt[k*64+d] = cl_w[i]; return; }
}

// ---------------- conv2: cp.async pipelined FFMA2 conv (emb, qkv, cl) ----------------
// OUTMODE: 1=NCHW; 2=NCHW+resid; 3=qkv (chan-last 288 + q/k bf16-pair hi/lo tiles)
template<int CIN, int COUT, int TILE_D, int KS, int CCH, int OUTMODE, int MAXB>
__global__ void __launch_bounds__(16*(TILE_D/4), MAXB)
conv2(const float* __restrict__ inA,
      const float* __restrict__ wt, const float* __restrict__ bias,
      float* __restrict__ out, uint32_t* __restrict__ o_qh, uint32_t* __restrict__ o_ql,
      uint32_t* __restrict__ o_kh, uint32_t* __restrict__ o_kl,
      const float* __restrict__ resid)
{
    constexpr int NT   = 16*(TILE_D/4);
    constexpr int KSQ  = KS*KS;
    constexpr int ROWS = (KS==3) ? 4 : 2;
    constexpr int IN_E = CCH*ROWS*64;
    constexpr int W_E  = CCH*KSQ*TILE_D;
    extern __shared__ float sm[];
    float* s_in = sm;
    float* s_w  = sm + 2*IN_E;

    const int tx  = threadIdx.x, ty = threadIdx.y;
    const int tid = ty*16 + tx;
    const int y0  = 2*blockIdx.y;
    const int z   = blockIdx.z;
    const int dblk = blockIdx.x*TILE_D;
    const int d0  = dblk + 4*ty;
    const int px0 = 4*tx;

    const float* pin = inA + (long)z*CIN*HW;

    const uint32_t s_in_b = (uint32_t)__cvta_generic_to_shared(s_in);
    const uint32_t s_w_b  = (uint32_t)__cvta_generic_to_shared(s_w);

    auto fill = [&](int ch, int buf) {
        const float* cbase = pin + (long)ch*CCH*HW;
        for (int e = tid; e < CCH*ROWS*16; e += NT) {
            int q  = e & 15;
            int r  = (e >> 4) % ROWS;
            int cc = e / (16*ROWS);
            int yy = (KS==3) ? (y0-1+r) : (y0+r);
            bool valid = (yy >= 0 && yy < HH);
            int yc = valid ? yy : 0;
            const float* src = cbase + cc*HW + yc*WW + q*4;
            uint32_t dst = s_in_b + (buf*IN_E + (cc*ROWS + r)*64 + q*4)*4u;
            cpa16(dst, src, valid);
        }
        const float* wbase = wt + ((long)ch*CCH*KSQ)*COUT + dblk;
        for (int e = tid; e < W_E/4; e += NT) {
            int qd = e % (TILE_D/4);
            int t  = e / (TILE_D/4);
            const float* src = wbase + (long)t*COUT + qd*4;
            uint32_t dst = s_w_b + (buf*W_E + t*TILE_D + qd*4)*4u;
            cpa16(dst, src, true);
        }
    };

    u64 acc2[2][2][4];
#pragma unroll
    for (int h=0; h<2; h++) {
        u64 bv = pk2(bias[d0+2*h], bias[d0+2*h+1]);
#pragma unroll
        for (int o=0; o<2; o++)
#pragma unroll
            for (int pj=0; pj<4; pj++) acc2[o][h][pj] = bv;
    }

    auto compute = [&](int buf) {
#pragma unroll
        for (int cc=0; cc<CCH; cc++) {
            const float* inrow = s_in + buf*IN_E + cc*ROWS*64;
            if (KS == 3) {
#pragma unroll
                for (int r=0; r<4; r++) {
                    const float* rw = inrow + r*64;
                    float e0 = rw[(tx==0) ? 0 : (px0-1)];
                    if (tx == 0) e0 = 0.f;
                    float4 m = *(const float4*)(rw + px0);
                    float e5 = rw[(tx==15) ? 63 : (px0+4)];
                    if (tx == 15) e5 = 0.f;
                    u64 a[6] = {pk(e0), pk(m.x), pk(m.y), pk(m.z), pk(m.w), pk(e5)};
#pragma unroll
                    for (int o=0; o<2; o++) {
                        const int dy = r - o;
                        if (dy < 0 || dy > 2) continue;
#pragma unroll
                        for (int dx=0; dx<3; dx++) {
                            const u64* wp = (const u64*)(s_w + buf*W_E
                                              + (cc*9 + dy*3 + dx)*TILE_D + 4*ty);
                            u64 w01 = wp[0], w23 = wp[1];
#pragma unroll
                            for (int pj=0; pj<4; pj++) {
                                fma2(acc2[o][0][pj], a[dx+pj], w01);
                                fma2(acc2[o][1][pj], a[dx+pj], w23);
                            }
                        }
                    }
                }
            } else {
                const u64* wp = (const u64*)(s_w + buf*W_E + cc*TILE_D + 4*ty);
                u64 w01 = wp[0], w23 = wp[1];
#pragma unroll
                for (int r=0; r<2; r++) {
                    float4 m = *(const float4*)(inrow + r*64 + px0);
                    u64 a4[4] = {pk(m.x), pk(m.y), pk(m.z), pk(m.w)};
#pragma unroll
                    for (int pj=0; pj<4; pj++) {
                        fma2(acc2[r][0][pj], a4[pj], w01);
                        fma2(acc2[r][1][pj], a4[pj], w23);
                    }
                }
            }
        }
    };

    constexpr int NCH = CIN/CCH;
    fill(0, 0);
    cp_commit();
    for (int ch = 0; ch < NCH; ch++) {
        cp_wait<0>();
        __syncthreads();
        if (ch+1 < NCH) {
            fill(ch+1, (ch+1) & 1);
            cp_commit();
        }
        compute(ch & 1);
    }

#pragma unroll
    for (int o=0; o<2; o++) {
        float acc[4][4];
#pragma unroll
        for (int h=0; h<2; h++)
#pragma unroll
            for (int pj=0; pj<4; pj++) {
                float2 f = up2(acc2[o][h][pj]);
                acc[2*h][pj] = f.x; acc[2*h+1][pj] = f.y;
            }
        const int y = y0 + o;
        if (OUTMODE == 1) {
#pragma unroll
            for (int dj=0; dj<4; dj++) {
                *(float4*)&out[((long)z*COUT + d0+dj)*HW + y*WW + px0]
                    = make_float4(acc[dj][0], acc[dj][1], acc[dj][2], acc[dj][3]);
            }
        } else if (OUTMODE == 2) {
#pragma unroll
            for (int dj=0; dj<4; dj++) {
                long idx = ((long)z*COUT + d0+dj)*HW + y*WW + px0;
                float4 rr = *(const float4*)&resid[idx];
                *(float4*)&out[idx] = make_float4(acc[dj][0]+rr.x, acc[dj][1]+rr.y,
                                                  acc[dj][2]+rr.z, acc[dj][3]+rr.w);
            }
        } else {  // OUTMODE 3: qkv
#pragma unroll
            for (int pj=0; pj<4; pj++) {
                float4 ov = make_float4(acc[0][pj], acc[1][pj], acc[2][pj], acc[3][pj]);
                *(float4*)&out[((long)z*HW + y*WW + px0 + pj)*288 + d0] = ov;
            }
            if (d0 < 192) {
                uint32_t* oh = (d0 < 96) ? o_qh : o_kh;
                uint32_t* ol = (d0 < 96) ? o_ql : o_kl;
                int c = (d0 < 96) ? d0 : (d0 - 96);
#pragma unroll
                for (int pj=0; pj<4; pj++) {
                    float a0 = acc[0][pj], a1 = acc[1][pj], a2 = acc[2][pj], a3 = acc[3][pj];
                    float h0 = bf_hi(a0), h1 = bf_hi(a1), h2 = bf_hi(a2), h3 = bf_hi(a3);
                    long base = ((long)(z*3 + (c>>5))*HW + (y*WW + px0 + pj))*16 + ((c & 31) >> 1);
                    *(uint2*)&oh[base] = make_uint2(bfpack(h0, h1), bfpack(h2, h3));
                    *(uint2*)&ol[base] = make_uint2(bfpack(a0-h0, a1-h1), bfpack(a2-h2, a3-h3));
                }
            }
        }
    }
}

// ---------------- generic 3xBF16 HMMA implicit-GEMM 3x3 conv, 4-stage pipeline ----------------
// m16n8k16 bf16 MMAs; smem bf16-pair u32, stride 20 (conflict-free).
// Block tile 128(M) x NTL*16(N), 8 warps = 4M x 2N, 1 block/SM, 4 cp.async stages.
// OUTM: 0 = channel-last fp32 (+bias); 1 = fp32 tile-32 (+bias, TWOIN selects buf);
//       2 = lrelu(+bias) then bf16 hi/lo split pair-tiles.
template<int NOUT, int NTL, int OUTM, bool TWOIN>
__global__ void __launch_bounds__(256, 1)
hmma_conv(const uint32_t* __restrict__ aA_hi, const uint32_t* __restrict__ aA_lo,
          const uint32_t* __restrict__ aB_hi, const uint32_t* __restrict__ aB_lo,
          const uint32_t* __restrict__ w1_hi, const uint32_t* __restrict__ w1_lo,
          const uint32_t* __restrict__ w2_hi, const uint32_t* __restrict__ w2_lo,
          const float* __restrict__ bias,
          float* __restrict__ outf, float* __restrict__ outf2,
          uint32_t* __restrict__ outu, uint32_t* __restrict__ outul)
{
    constexpr int AST = 20;                 // u32 per row (16 pairs + pad)
    constexpr int A_E = 128*AST;            // 2560 u32 per buffer
    constexpr int BROWS = NTL*16;
    constexpr int B_E = BROWS*AST;
    constexpr int NST = 4;                  // pipeline stages
    extern __shared__ uint32_t smu[];
    uint32_t* sAh = smu;
    uint32_t* sAl = smu + NST*A_E;
    uint32_t* sBh = smu + 2*NST*A_E;
    uint32_t* sBl = smu + 2*NST*A_E + NST*B_E;

    const int tid = threadIdx.x;
    const int wid = tid >> 5, lane = tid & 31;
    const int z   = blockIdx.z;
    const int p0  = blockIdx.x * 128;
    const int n0  = blockIdx.y * BROWS;
    const int wm  = (wid & 3) * 32;
    const int wn  = (wid >> 2) * (NTL*8);
    const int gq  = lane >> 2;
    const int tg  = lane & 3;

    const uint32_t* a_hi = aA_hi; const uint32_t* a_lo = aA_lo;
    const uint32_t* b_hi = w1_hi; const uint32_t* b_lo = w1_lo;
    int f = z;
    if (TWOIN && z >= 12) {
        a_hi = aB_hi; a_lo = aB_lo; b_hi = w2_hi; b_lo = w2_lo; f = z - 12;
    }

    const uint32_t sAh_b = (uint32_t)__cvta_generic_to_shared(sAh);
    const uint32_t sAl_b = (uint32_t)__cvta_generic_to_shared(sAl);
    const uint32_t sBh_b = (uint32_t)__cvta_generic_to_shared(sBh);
    const uint32_t sBl_b = (uint32_t)__cvta_generic_to_shared(sBl);

    auto fillA = [&](int kc, int buf) {
        int tap = kc/3, cb = kc - tap*3;
        int dy = tap/3 - 1, dx = tap - (tap/3)*3 - 1;
        long cboff = ((long)(f*3 + cb))*HW*16;
        const uint32_t* ah = a_hi + cboff;
        const uint32_t* al = a_lo + cboff;
#pragma unroll
        for (int e = tid; e < 512; e += 256) {
            int m = e >> 2, seg = e & 3;
            int py = ((p0+m) >> 6) + dy;
            int px = ((p0+m) & 63) + dx;
            bool v = (py >= 0 && py < 64 && px >= 0 && px < 64);
            int pyc = min(max(py,0),63), pxc = min(max(px,0),63);
            long so = ((long)(pyc*64 + pxc))*16 + seg*4;
            uint32_t doff = (buf*A_E + m*AST + seg*4)*4u;
            cpa16(sAh_b + doff, ah + so, v);
            cpa16(sAl_b + doff, al + so, v);
        }
    };
    auto fillB = [&](int kc, int buf) {
#pragma unroll
        for (int e = tid; e < BROWS*4; e += 256) {
            int n = e >> 2, seg = e & 3;
            int ng = n0 + n;
            bool v = (ng < NOUT);
            int ns = v ? ng : 0;
            long so = (long)ns*432 + kc*16 + seg*4;
            uint32_t doff = (buf*B_E + n*AST + seg*4)*4u;
            cpa16(sBh_b + doff, b_hi + so, v);
            cpa16(sBl_b + doff, b_lo + so, v);
        }
    };

    float d[2][NTL][4];
#pragma unroll
    for (int mt=0; mt<2; mt++)
#pragma unroll
        for (int nt=0; nt<NTL; nt++)
#pragma unroll
            for (int r=0; r<4; r++) d[mt][nt][r] = 0.f;

    // 4-stage prologue: fills for chunks 0..2 in flight
    fillA(0, 0); fillB(0, 0); cp_commit();
    fillA(1, 1); fillB(1, 1); cp_commit();
    fillA(2, 2); fillB(2, 2); cp_commit();

    for (int ch = 0; ch < 27; ch++) {
        cp_wait<2>();            // guarantees fill(ch) complete (uniform 1 group/iter)
        __syncthreads();         // publish fill(ch); fence compute(ch-1) before overwrite
        if (ch+3 < 27) {
            fillA(ch+3, (ch+3) & 3);
            fillB(ch+3, (ch+3) & 3);
        }
        cp_commit();             // unconditional: keeps group accounting uniform
        const int buf = ch & 3;
        const uint32_t* Ah = sAh + buf*A_E;
        const uint32_t* Al = sAl + buf*A_E;
        const uint32_t* Bh = sBh + buf*B_E;
        const uint32_t* Bl = sBl + buf*B_E;
#pragma unroll
        for (int s=0; s<2; s++) {
            const int kp = s*8;              // pair offset within chunk
            uint32_t ah[2][4], al[2][4];
#pragma unroll
            for (int mt=0; mt<2; mt++) {
                int r = wm + mt*16 + gq;
                ah[mt][0] = Ah[r*AST + kp + tg];
                ah[mt][1] = Ah[(r+8)*AST + kp + tg];
                ah[mt][2] = Ah[r*AST + kp + 4 + tg];
                ah[mt][3] = Ah[(r+8)*AST + kp + 4 + tg];
                al[mt][0] = Al[r*AST + kp + tg];
                al[mt][1] = Al[(r+8)*AST + kp + tg];
                al[mt][2] = Al[r*AST + kp + 4 + tg];
                al[mt][3] = Al[(r+8)*AST + kp + 4 + tg];
            }
#pragma unroll
            for (int nt=0; nt<NTL; nt++) {
                int n = wn + nt*8 + gq;
                uint32_t bh0 = Bh[n*AST + kp + tg];
                uint32_t bh1 = Bh[n*AST + kp + 4 + tg];
                uint32_t bl0 = Bl[n*AST + kp + tg];
                uint32_t bl1 = Bl[n*AST + kp + 4 + tg];
                mma_bf16(d[0][nt], ah[0], bh0, bh1);
                mma_bf16(d[1][nt], ah[1], bh0, bh1);
                mma_bf16(d[0][nt], al[0], bh0, bh1);
                mma_bf16(d[1][nt], al[1], bh0, bh1);
                mma_bf16(d[0][nt], ah[0], bl0, bl1);
                mma_bf16(d[1][nt], ah[1], bl0, bl1);
            }
        }
    }

    // epilogue
    if (OUTM == 0) {
#pragma unroll
        for (int mt=0; mt<2; mt++) {
            int row = p0 + wm + mt*16 + gq;
            float* op0 = outf + ((long)z*HW + row)*NOUT;
            float* op1 = op0 + 8L*NOUT;
#pragma unroll
            for (int nt=0; nt<NTL; nt++) {
                int col = n0 + wn + nt*8 + tg*2;
                if (col < NOUT) {
                    float bx = __ldg(bias + col), by = __ldg(bias + col + 1);
                    *(float2*)(op0 + col) = make_float2(d[mt][nt][0] + bx, d[mt][nt][1] + by);
                    *(float2*)(op1 + col) = make_float2(d[mt][nt][2] + bx, d[mt][nt][3] + by);
                }
            }
        }
    } else if (OUTM == 1) {
        float* o = (TWOIN && z >= 12) ? outf2 : outf;
#pragma unroll
        for (int mt=0; mt<2; mt++) {
            int row = p0 + wm + mt*16 + gq;
#pragma unroll
            for (int nt=0; nt<NTL; nt++) {
                int col = n0 + wn + nt*8 + tg*2;
                if (col < NOUT) {
                    float bx = __ldg(bias + col), by = __ldg(bias + col + 1);
                    long b0i = ((long)(f*3 + (col>>5))*HW + row)*32 + (col & 31);
                    *(float2*)(o + b0i)        = make_float2(d[mt][nt][0] + bx, d[mt][nt][1] + by);
                    *(float2*)(o + b0i + 8*32) = make_float2(d[mt][nt][2] + bx, d[mt][nt][3] + by);
                }
            }
        }
    } else {  // OUTM == 2: lrelu + bf16 hi/lo split pair tiles
#pragma unroll
        for (int mt=0; mt<2; mt++) {
            int row = p0 + wm + mt*16 + gq;
#pragma unroll
            for (int nt=0; nt<NTL; nt++) {
                int col = n0 + wn + nt*8 + tg*2;
                if (col < NOUT) {
                    float bx = __ldg(bias + col), by = __ldg(bias + col + 1);
                    float v0 = d[mt][nt][0] + bx; v0 = (v0>=0.f)?v0:0.1f*v0;
                    float v1 = d[mt][nt][1] + by; v1 = (v1>=0.f)?v1:0.1f*v1;
                    float v2 = d[mt][nt][2] + bx; v2 = (v2>=0.f)?v2:0.1f*v2;
                    float v3 = d[mt][nt][3] + by; v3 = (v3>=0.f)?v3:0.1f*v3;
                    float h0 = bf_hi(v0), h1 = bf_hi(v1);
                    float h2 = bf_hi(v2), h3 = bf_hi(v3);
                    long b0i = ((long)(z*3 + (col>>5))*HW + row)*16 + ((col & 31) >> 1);
                    outu [b0i]        = bfpack(h0, h1);
                    outul[b0i]        = bfpack(v0-h0, v1-h1);
                    outu [b0i + 8*16] = bfpack(h2, h3);
                    outul[b0i + 8*16] = bfpack(v2-h2, v3-h3);
                }
            }
        }
    }
}

// ---------------- sum: off1 = lrelu(aq[jj]+ak[ii]+oc1_b), bf16 hi/lo pairs ----------------
__global__ void sum_k(const float* __restrict__ aq, const float* __restrict__ ak,
                      const float* __restrict__ bias,
                      uint32_t* __restrict__ oh, uint32_t* __restrict__ ol)
{
    long i = (long)blockIdx.x*256 + threadIdx.x;   // 4-channel groups
    const long TOT = 24L*3*4096*8;
    if (i >= TOT) return;
    int seg = (int)(i & 7);
    long r = i >> 3;
    int p = (int)(r & 4095); r >>= 12;
    int cb = (int)(r % 3);
    int img = (int)(r / 3);
    int pair = img >> 2, b = img & 3;
    int jj = pair >> 1, l = pair & 1;
    int ii = l ? ((jj==2) ? 1 : 2) : ((jj==0) ? 1 : 0);
    long qi = (((long)(b*3+jj)*3 + cb)*HW + p)*32 + seg*4;
    long ki = (((long)(b*3+ii)*3 + cb)*HW + p)*32 + seg*4;
    float4 a = *(const float4*)&aq[qi];
    float4 k = *(const float4*)&ak[ki];
    int c = cb*32 + seg*4;
    float t0 = a.x + k.x + bias[c+0]; t0 = (t0>=0.f)?t0:0.1f*t0;
    float t1 = a.y + k.y + bias[c+1]; t1 = (t1>=0.f)?t1:0.1f*t1;
    float t2 = a.z + k.z + bias[c+2]; t2 = (t2>=0.f)?t2:0.1f*t2;
    float t3 = a.w + k.w + bias[c+3]; t3 = (t3>=0.f)?t3:0.1f*t3;
    float h0 = bf_hi(t0), h1 = bf_hi(t1), h2 = bf_hi(t2), h3 = bf_hi(t3);
    long oidx = (((long)img*3 + cb)*HW + p)*16 + seg*2;
    *(uint2*)&oh[oidx] = make_uint2(bfpack(h0, h1), bfpack(h2, h3));
    *(uint2*)&ol[oidx] = make_uint2(bfpack(t0-h0, t1-h1), bfpack(t2-h2, t3-h3));
}

// ---------------- deformable top-2 attention ----------------
__global__ void __launch_bounds__(128) attn_k(
    const float* __restrict__ qkv,
    const float* __restrict__ om_all,
    float* __restrict__ w_all, float* __restrict__ v_all)
{
    __shared__ __align__(16) float4 s_wgt[4][72];
    __shared__ __align__(16) int4   s_off[4][72];
    const int warp = threadIdx.x >> 5;
    const int lane = threadIdx.x & 31;
    const int p = blockIdx.x*4 + warp;
    const int b = blockIdx.y;
    const int pair = blockIdx.z;
    const int jj = pair >> 1;
    const int l  = pair & 1;
    const int ii = l ? ((jj==2) ? 1 : 2) : ((jj==0) ? 1 : 0);
    const int y = p >> 6, x = p & 63;
    const float* ombase = om_all + ((pair*4 + b)*HW + (long)p)*216;

    for (int t = lane; t < 72; t += 32) {
        float oy = ombase[t];
        float ox = ombase[72 + t];
        float mm = ombase[144 + t];
        int n = t % 9;
        float m  = 1.f/(1.f + expf(-mm));
        float py = oy + (float)(n/3 - 1 + y);
        float px = ox + (float)(n%3 - 1 + x);
        float y0f = floorf(py), x0f = floorf(px);
        float wy = py - y0f, wx = px - x0f;
        int iy0 = (int)y0f, ix0 = (int)x0f;
        int iy1 = iy0 + 1, ix1 = ix0 + 1;
        float vy0 = (iy0 >= 0 && iy0 < HH) ? 1.f : 0.f;
        float vy1 = (iy1 >= 0 && iy1 < HH) ? 1.f : 0.f;
        float vx0 = (ix0 >= 0 && ix0 < WW) ? 1.f : 0.f;
        float vx1 = (ix1 >= 0 && ix1 < WW) ? 1.f : 0.f;
        int cy0 = min(max(iy0,0),HH-1), cy1 = min(max(iy1,0),HH-1);
        int cx0 = min(max(ix0,0),WW-1), cx1 = min(max(ix1,0),WW-1);
        float wy0 = 1.f - wy, wx0 = 1.f - wx;
        s_wgt[warp][t] = make_float4(m*wy0*wx0*vy0*vx0, m*wy0*wx *vy0*vx1,
                                     m*wy *wx0*vy1*vx0, m*wy *wx *vy1*vx1);
        s_off[warp][t] = make_int4((cy0*WW+cx0)*288, (cy0*WW+cx1)*288,
                                   (cy1*WW+cx0)*288, (cy1*WW+cx1)*288);
    }
    __syncwarp();

    const bool act = (lane < 24);
    const int g = lane / 3;
    const float* qp = qkv + (((b*3+jj)*HW + (long)p)*288);
    float4 qv = make_float4(0,0,0,0);
    if (act) qv = __ldg((const float4*)(qp + 4*lane));
    const float* kb = qkv + (b*3+ii)*(long)HW*288 + 96 + 4*lane;

    float rel[9];
#pragma unroll
    for (int n=0; n<9; n++) {
        float part = 0.f;
        if (act) {
            float4 W = s_wgt[warp][g*9+n];
            int4   O = s_off[warp][g*9+n];
            float4 k0 = __ldg((const float4*)(kb + O.x));
            float4 k1 = __ldg((const float4*)(kb + O.y));
            float4 k2 = __ldg((const float4*)(kb + O.z));
            float4 k3 = __ldg((const float4*)(kb + O.w));
            float sx = W.x*k0.x + W.y*k1.x + W.z*k2.x + W.w*k3.x;
            float sy = W.x*k0.y + W.y*k1.y + W.z*k2.y + W.w*k3.y;
            float sz = W.x*k0.z + W.y*k1.z + W.z*k2.z + W.w*k3.z;
            float sw = W.x*k0.w + W.y*k1.w + W.z*k2.w + W.w*k3.w;
            part = sx*qv.x + sy*qv.y + sz*qv.z + sw*qv.w;
        }
#pragma unroll
        for (int o=16; o>0; o>>=1) part += __shfl_xor_sync(0xffffffffu, part, o);
        rel[n] = part;
    }

    float b1 = rel[0]; int i1 = 0; float b2 = -1e30f; int i2 = 0;
#pragma unroll
    for (int n=1; n<9; n++) {
        if (rel[n] > b1)      { b2 = b1; i2 = i1; b1 = rel[n]; i1 = n; }
        else if (rel[n] > b2) { b2 = rel[n]; i2 = n; }
    }
    float c1 = 1.f/(1.f + expf(b2 - b1));
    float c2 = 1.f - c1;
    if (lane == 0) w_all[(pair*4 + b)*HW + p] = c1*b1 + c2*b2;

    if (act) {
        const float* vb = kb + 96;
        float4 W1 = s_wgt[warp][g*9+i1]; int4 O1 = s_off[warp][g*9+i1];
        float4 W2 = s_wgt[warp][g*9+i2]; int4 O2 = s_off[warp][g*9+i2];
        float4 a0 = __ldg((const float4*)(vb + O1.x));
        float4 a1 = __ldg((const float4*)(vb + O1.y));
        float4 a2 = __ldg((const float4*)(vb + O1.z));
        float4 a3 = __ldg((const float4*)(vb + O1.w));
        float4 b0 = __ldg((const float4*)(vb + O2.x));
        float4 bb1= __ldg((const float4*)(vb + O2.y));
        float4 b2v= __ldg((const float4*)(vb + O2.z));
        float4 b3 = __ldg((const float4*)(vb + O2.w));
        float4 ov;
        ov.x = c1*(W1.x*a0.x + W1.y*a1.x + W1.z*a2.x + W1.w*a3.x)
             + c2*(W2.x*b0.x + W2.y*bb1.x + W2.z*b2v.x + W2.w*b3.x);
        ov.y = c1*(W1.x*a0.y + W1.y*a1.y + W1.z*a2.y + W1.w*a3.y)
             + c2*(W2.x*b0.y + W2.y*bb1.y + W2.z*b2v.y + W2.w*b3.y);
        ov.z = c1*(W1.x*a0.z + W1.y*a1.z + W1.z*a2.z + W1.w*a3.z)
             + c2*(W2.x*b0.z + W2.y*bb1.z + W2.z*b2v.z + W2.w*b3.z);
        ov.w = c1*(W1.x*a0.w + W1.y*a1.w + W1.z*a2.w + W1.w*a3.w)
             + c2*(W2.x*b0.w + W2.y*bb1.w + W2.z*b2v.w + W2.w*b3.w);
        *(float4*)(v_all + ((pair*4 + b)*HW + (long)p)*96 + 4*lane) = ov;
    }
}

// ---------------- fuse with smem transpose ----------------
__global__ void __launch_bounds__(384) fuse_k2(const float* __restrict__ w_all,
                                               const float* __restrict__ v_all,
                                               float* __restrict__ f)
{
    __shared__ float s[96][33];
    const int t = threadIdx.x;
    const int p0 = blockIdx.x*32;
    const int img = blockIdx.y;
    const int jj = img % 3, b = img / 3;
    const int z0 = (jj*2)*4 + b, z1 = (jj*2+1)*4 + b;
#pragma unroll
    for (int k=0; k<8; k++) {
        int e = t + k*384;
        int c = e % 96, pp = e / 96;
        int p = p0 + pp;
        float w0 = w_all[z0*HW + p];
        float w1 = w_all[z1*HW + p];
        float mx = fmaxf(w0, w1);
        float e0 = expf(w0-mx), e1 = expf(w1-mx);
        float inv = 1.f/(e0+e1);
        float v0 = v_all[((long)z0*HW + p)*96 + c];
        float v1 = v_all[((long)z1*HW + p)*96 + c];
        s[c][pp] = (e0*v0 + e1*v1)*inv;
    }
    __syncthreads();
#pragma unroll
    for (int k=0; k<8; k++) {
        int e = t + k*384;
        int pp = e % 32, c = e / 32;
        f[((long)img*96 + c)*HW + p0 + pp] = s[c][pp];
    }
}

// ---------------- host ----------------
static void* symaddr(const void* s) {
    void* p = nullptr;
    cudaGetSymbolAddress(&p, s);
    return p;
}

extern "C" void kernel_launch(void* const* d_in, const int* in_sizes, int n_in,
                              void* d_out, int out_size)
{
    const float* fea   = (const float*)d_in[0];
    const float* cf_w  = (const float*)d_in[1];
    const float* cf_b  = (const float*)d_in[2];
    const float* wq    = (const float*)d_in[3];
    const float* bq    = (const float*)d_in[4];
    const float* wk    = (const float*)d_in[5];
    const float* bk    = (const float*)d_in[6];
    const float* wv    = (const float*)d_in[7];
    const float* bv    = (const float*)d_in[8];
    const float* oc1_w = (const float*)d_in[9];
    const float* oc1_b = (const float*)d_in[10];
    const float* oc2_w = (const float*)d_in[11];
    const float* oc2_b = (const float*)d_in[12];
    const float* om_w  = (const float*)d_in[13];
    const float* om_b  = (const float*)d_in[14];
    const float* cl_w  = (const float*)d_in[15];
    const float* cl_b  = (const float*)d_in[16];
    float* out = (float*)d_out;

    float*    emb   = (float*)symaddr(g_emb);
    float*    qkv   = (float*)symaddr(g_qkv);
    uint32_t* q32h  = (uint32_t*)symaddr(g_q32h);
    uint32_t* q32l  = (uint32_t*)symaddr(g_q32l);
    uint32_t* k32h  = (uint32_t*)symaddr(g_k32h);
    uint32_t* k32l  = (uint32_t*)symaddr(g_k32l);
    float*    aq32  = (float*)symaddr(g_aq32);
    float*    ak32  = (float*)symaddr(g_ak32);
    uint32_t* off1h = (uint32_t*)symaddr(g_off1h);
    uint32_t* off1l = (uint32_t*)symaddr(g_off1l);
    uint32_t* off2h = (uint32_t*)symaddr(g_off2h);
    uint32_t* off2l = (uint32_t*)symaddr(g_off2l);
    float*    omb   = (float*)symaddr(g_om);
    float*    wall  = (float*)symaddr(g_wall);
    float*    vall  = (float*)symaddr(g_vall);
    float*    fbuf  = (float*)symaddr(g_f);
    float*    cfwt  = (float*)symaddr(g_cfwt);
    float*    qkvwt = (float*)symaddr(g_qkvwt);
    float*    qkvb  = (float*)symaddr(g_qkvb);
    uint32_t* oc1qh = (uint32_t*)symaddr(g_oc1qh);
    uint32_t* oc1ql = (uint32_t*)symaddr(g_oc1ql);
    uint32_t* oc1kh = (uint32_t*)symaddr(g_oc1kh);
    uint32_t* oc1kl = (uint32_t*)symaddr(g_oc1kl);
    uint32_t* oc2h  = (uint32_t*)symaddr(g_oc2h);
    uint32_t* oc2l  = (uint32_t*)symaddr(g_oc2l);
    uint32_t* omwth = (uint32_t*)symaddr(g_omwth);
    uint32_t* omwtl = (uint32_t*)symaddr(g_omwtl);
    float*    clwt  = (float*)symaddr(g_clwt);
    float*    zero  = (float*)symaddr(g_zero);

    const int SM48_3 = 2*(8*4*64 + 8*9*48)*4;      // 44032
    const int SM48_1 = 2*(8*2*64 + 8*1*48)*4;      // 11264
    const int SM32_3 = 2*(8*4*64 + 8*9*32)*4;      // 34816
    const int SM_BF6 = (4*2560*2 + 4*1920*2)*4;    // 143360 (oc1/oc2, 4 stages)
    const int SM_BF7 = (4*2560*2 + 4*2240*2)*4;    // 153600 (om, 4 stages)

    static bool attr_done = false;
    if (!attr_done) {
        cudaFuncSetAttribute((const void*)hmma_conv<216,7,0,false>,
                             cudaFuncAttributeMaxDynamicSharedMemorySize, SM_BF7);
        cudaFuncSetAttribute((const void*)hmma_conv<96,6,1,true>,
                             cudaFuncAttributeMaxDynamicSharedMemorySize, SM_BF6);
        cudaFuncSetAttribute((const void*)hmma_conv<96,6,2,false>,
                             cudaFuncAttributeMaxDynamicSharedMemorySize, SM_BF6);
        attr_done = true;
    }

    // 1) weight prep (bf16 hi/lo pair splits)
    prep_all<<<1319, 256>>>(cf_w, wq, wk, wv, bq, bk, bv, oc1_w, oc2_w, om_w, cl_w);

    // 2) emb = conv3x3(fea): NCHW -> NCHW (FFMA2, exact)
    conv2<64,96,48,3,8,1,5><<<dim3(2,32,12), dim3(16,12), SM48_3>>>(
        fea, cfwt, cf_b, emb, nullptr, nullptr, nullptr, nullptr, nullptr);

    // 3) qkv = 1x1(emb): chan-last 288 + q/k bf16 hi/lo pair tiles (FFMA2)
    conv2<96,288,48,1,8,3,5><<<dim3(6,32,12), dim3(16,12), SM48_1>>>(
        emb, qkvwt, qkvb, qkv, q32h, q32l, k32h, k32l, nullptr);

    // 4) oc1 via 3xBF16 HMMA (4-stage): q-frames (z<12) -> aq32, k -> ak32
    hmma_conv<96,6,1,true><<<dim3(32,1,24), 256, SM_BF6>>>(
        q32h, q32l, k32h, k32l, oc1qh, oc1ql, oc1kh, oc1kl, zero,
        aq32, ak32, nullptr, nullptr);

    // 5) off1 = lrelu(aq[jj]+ak[ii]+oc1_b), bf16 hi/lo pairs
    sum_k<<<9216, 256>>>(aq32, ak32, oc1_b, off1h, off1l);

    // 6) oc2 via 3xBF16 HMMA (4-stage, +lrelu, bf16 hi/lo out)
    hmma_conv<96,6,2,false><<<dim3(32,1,24), 256, SM_BF6>>>(
        off1h, off1l, nullptr, nullptr, oc2h, oc2l, nullptr, nullptr,
        oc2_b, nullptr, nullptr, off2h, off2l);

    // 7) om via 3xBF16 HMMA (4-stage): channel-last 216 fp32
    hmma_conv<216,7,0,false><<<dim3(32,2,24), 256, SM_BF7>>>(
        off2h, off2l, nullptr, nullptr, omwth, omwtl, nullptr, nullptr,
        om_b, omb, nullptr, nullptr, nullptr);

    // 8) attention
    attn_k<<<dim3(1024,4,6), 128>>>(qkv, omb, wall, vall);

    // 9) fuse -> NCHW fbuf
    fuse_k2<<<dim3(128,12), 384>>>(wall, vall, fbuf);

    // 10) cl conv: NCHW -> NCHW out + residual (FFMA2)
    conv2<96,64,32,3,8,2,6><<<dim3(2,32,12), dim3(16,8), SM32_3>>>(
        fbuf, clwt, cl_b, out, nullptr, nullptr, nullptr, nullptr, fea);

    (void)in_sizes; (void)n_in; (void)out_size;
}

// round 16
// speedup vs baseline: 1.0406x; 1.0406x over previous
#include <cuda_runtime.h>
#include <math.h>
#include <stdint.h>

#define HW 4096
#define WW 64
#define HH 64

typedef unsigned long long u64;

// ---------------- packed f32x2 helpers ----------------
__device__ __forceinline__ u64 pk(float v) {
    u64 r; asm("mov.b64 %0, {%1, %1};" : "=l"(r) : "f"(v)); return r;
}
__device__ __forceinline__ u64 pk2(float a, float b) {
    u64 r; asm("mov.b64 %0, {%1, %2};" : "=l"(r) : "f"(a), "f"(b)); return r;
}
__device__ __forceinline__ void fma2(u64& d, u64 a, u64 b) {
    asm("fma.rn.f32x2 %0, %1, %2, %0;" : "+l"(d) : "l"(a), "l"(b));
}
__device__ __forceinline__ float2 up2(u64 v) {
    float2 f; asm("mov.b64 {%0, %1}, %2;" : "=f"(f.x), "=f"(f.y) : "l"(v)); return f;
}

// ---------------- cp.async helpers ----------------
__device__ __forceinline__ void cpa16(uint32_t dst, const void* src, bool v) {
    int sz = v ? 16 : 0;
    asm volatile("cp.async.ca.shared.global [%0], [%1], 16, %2;" :: "r"(dst), "l"(src), "r"(sz));
}
__device__ __forceinline__ void cp_commit() { asm volatile("cp.async.commit_group;"); }
template<int N> __device__ __forceinline__ void cp_wait() {
    asm volatile("cp.async.wait_group %0;" :: "n"(N));
}

// ---------------- bf16 helpers (sm_80+ baseline PTX) ----------------
__device__ __forceinline__ uint32_t bfpack(float e0, float e1) {
    uint32_t r; asm("cvt.rn.bf16x2.f32 %0, %1, %2;" : "=r"(r) : "f"(e1), "f"(e0));
    return r;
}
__device__ __forceinline__ float bf_hi(float x) {
    uint32_t u; asm("cvt.rn.bf16x2.f32 %0, %1, %1;" : "=r"(u) : "f"(x));
    return __uint_as_float(u << 16);
}
__device__ __forceinline__ void mma_bf16(float* d, const uint32_t* a,
                                         uint32_t b0, uint32_t b1) {
    asm volatile(
        "mma.sync.aligned.m16n8k16.row.col.f32.bf16.bf16.f32 "
        "{%0,%1,%2,%3}, {%4,%5,%6,%7}, {%8,%9}, {%0,%1,%2,%3};"
        : "+f"(d[0]), "+f"(d[1]), "+f"(d[2]), "+f"(d[3])
        : "r"(a[0]), "r"(a[1]), "r"(a[2]), "r"(a[3]), "r"(b0), "r"(b1));
}

// ---------------- device scratch ----------------
__device__ float    g_emb [12L*96*HW];       // NCHW
__device__ float    g_qkv [12L*HW*288];      // channel-last (attn)
__device__ uint32_t g_q32h[12L*3*HW*16];     // q tile bf16-pairs hi
__device__ uint32_t g_q32l[12L*3*HW*16];
__device__ uint32_t g_k32h[12L*3*HW*16];
__device__ uint32_t g_k32l[12L*3*HW*16];
__device__ float    g_aq32[12L*3*HW*32];     // oc1(q) out, fp32 tile-32
__device__ float    g_ak32[12L*3*HW*32];
__device__ uint32_t g_off1h[24L*3*HW*16];    // lrelu(aq+ak+b), bf16-pairs
__device__ uint32_t g_off1l[24L*3*HW*16];
__device__ uint32_t g_off2h[24L*3*HW*16];
__device__ uint32_t g_off2l[24L*3*HW*16];
__device__ float    g_om  [24L*HW*216];      // channel-last (attn)
__device__ float    g_wall[24L*HW];
__device__ float    g_vall[24L*HW*96];
__device__ float    g_f   [12L*96*HW];       // NCHW
__device__ float    g_cfwt [64*9*96];
__device__ float    g_qkvwt[96*288];
__device__ float    g_qkvb [288];
__device__ uint32_t g_oc1qh[96*432];         // bf16-pair weights, [cout][tap*48+cinp]
__device__ uint32_t g_oc1ql[96*432];
__device__ uint32_t g_oc1kh[96*432];
__device__ uint32_t g_oc1kl[96*432];
__device__ uint32_t g_oc2h [96*432];
__device__ uint32_t g_oc2l [96*432];
__device__ uint32_t g_omwth[216*432];
__device__ uint32_t g_omwtl[216*432];
__device__ float    g_clwt [96*9*64];
__device__ float    g_zero [256];

// ---------------- single prep kernel ----------------
__global__ void prep_all(const float* __restrict__ cf_w,
                         const float* __restrict__ wq, const float* __restrict__ wk,
                         const float* __restrict__ wv,
                         const float* __restrict__ bq, const float* __restrict__ bk,
                         const float* __restrict__ bv,
                         const float* __restrict__ oc1_w, const float* __restrict__ oc2_w,
                         const float* __restrict__ om_w,  const float* __restrict__ cl_w)
{
    int i = blockIdx.x*256 + threadIdx.x;
    if (i < 55296) { int d = i/576, k = i%576; g_cfwt[k*96+d] = cf_w[i]; return; }
    i -= 55296;
    if (i < 9216) {
        int d = i/96, c = i%96;
        g_qkvwt[c*288 + d]       = wq[i];
        g_qkvwt[c*288 + 96 + d]  = wk[i];
        g_qkvwt[c*288 + 192 + d] = wv[i];
        return;
    }
    i -= 9216;
    if (i < 96) { g_qkvb[i] = bq[i]; g_qkvb[96+i] = bk[i]; g_qkvb[192+i] = bv[i]; return; }
    i -= 96;
    if (i < 82944) {   // oc1: pairs over 192 cin
        int d = i/864, rem = i%864, cp = rem/9, tap = rem%9;
        int cin0 = 2*cp;
        float w0 = oc1_w[d*1728 + cin0*9 + tap];
        float w1 = oc1_w[d*1728 + (cin0+1)*9 + tap];
        float h0 = bf_hi(w0), h1 = bf_hi(w1);
        uint32_t hp = bfpack(h0, h1);
        uint32_t lp = bfpack(w0-h0, w1-h1);
        if (cin0 < 96) { int idx = d*432 + tap*48 + cp;      g_oc1qh[idx]=hp; g_oc1ql[idx]=lp; }
        else           { int idx = d*432 + tap*48 + (cp-48); g_oc1kh[idx]=hp; g_oc1kl[idx]=lp; }
        return;
    }
    i -= 82944;
    if (i < 41472) {   // oc2
        int d = i/432, rem = i%432, cp = rem/9, tap = rem%9;
        int cin0 = 2*cp;
        float w0 = oc2_w[d*864 + cin0*9 + tap];
        float w1 = oc2_w[d*864 + (cin0+1)*9 + tap];
        float h0 = bf_hi(w0), h1 = bf_hi(w1);
        int idx = d*432 + tap*48 + cp;
        g_oc2h[idx] = bfpack(h0, h1);
        g_oc2l[idx] = bfpack(w0-h0, w1-h1);
        return;
    }
    i -= 41472;
    if (i < 93312) {   // om
        int d = i/432, rem = i%432, cp = rem/9, tap = rem%9;
        int cin0 = 2*cp;
        float w0 = om_w[d*864 + cin0*9 + tap];
        float w1 = om_w[d*864 + (cin0+1)*9 + tap];
        float h0 = bf_hi(w0), h1 = bf_hi(w1);
        int idx = d*432 + tap*48 + cp;
        g_omwth[idx] = bfpack(h0, h1);
        g_omwtl[idx] = bfpack(w0-h0, w1-h1);
        return;
    }
    i -= 93312;
    if (i < 55296) { int d = i/864, k = i%864; g_clwt[k*64+d] = cl_w[i]; return; }
}

// ---------------- conv2: cp.async pipelined FFMA2 conv (emb, qkv, cl) ----------------
// OUTMODE: 1=NCHW; 2=NCHW+resid; 3=qkv (chan-last 288 + q/k bf16-pair hi/lo tiles)
template<int CIN, int COUT, int TILE_D, int KS, int CCH, int OUTMODE, int MAXB>
__global__ void __launch_bounds__(16*(TILE_D/4), MAXB)
conv2(const float* __restrict__ inA,
      const float* __restrict__ wt, const float* __restrict__ bias,
      float* __restrict__ out, uint32_t* __restrict__ o_qh, uint32_t* __restrict__ o_ql,
      uint32_t* __restrict__ o_kh, uint32_t* __restrict__ o_kl,
      const float* __restrict__ resid)
{
    constexpr int NT   = 16*(TILE_D/4);
    constexpr int KSQ  = KS*KS;
    constexpr int ROWS = (KS==3) ? 4 : 2;
    constexpr int IN_E = CCH*ROWS*64;
    constexpr int W_E  = CCH*KSQ*TILE_D;
    extern __shared__ float sm[];
    float* s_in = sm;
    float* s_w  = sm + 2*IN_E;

    const int tx  = threadIdx.x, ty = threadIdx.y;
    const int tid = ty*16 + tx;
    const int y0  = 2*blockIdx.y;
    const int z   = blockIdx.z;
    const int dblk = blockIdx.x*TILE_D;
    const int d0  = dblk + 4*ty;
    const int px0 = 4*tx;

    const float* pin = inA + (long)z*CIN*HW;

    const uint32_t s_in_b = (uint32_t)__cvta_generic_to_shared(s_in);
    const uint32_t s_w_b  = (uint32_t)__cvta_generic_to_shared(s_w);

    auto fill = [&](int ch, int buf) {
        const float* cbase = pin + (long)ch*CCH*HW;
        for (int e = tid; e < CCH*ROWS*16; e += NT) {
            int q  = e & 15;
            int r  = (e >> 4) % ROWS;
            int cc = e / (16*ROWS);
            int yy = (KS==3) ? (y0-1+r) : (y0+r);
            bool valid = (yy >= 0 && yy < HH);
            int yc = valid ? yy : 0;
            const float* src = cbase + cc*HW + yc*WW + q*4;
            uint32_t dst = s_in_b + (buf*IN_E + (cc*ROWS + r)*64 + q*4)*4u;
            cpa16(dst, src, valid);
        }
        const float* wbase = wt + ((long)ch*CCH*KSQ)*COUT + dblk;
        for (int e = tid; e < W_E/4; e += NT) {
            int qd = e % (TILE_D/4);
            int t  = e / (TILE_D/4);
            const float* src = wbase + (long)t*COUT + qd*4;
            uint32_t dst = s_w_b + (buf*W_E + t*TILE_D + qd*4)*4u;
            cpa16(dst, src, true);
        }
    };

    u64 acc2[2][2][4];
#pragma unroll
    for (int h=0; h<2; h++) {
        u64 bv = pk2(bias[d0+2*h], bias[d0+2*h+1]);
#pragma unroll
        for (int o=0; o<2; o++)
#pragma unroll
            for (int pj=0; pj<4; pj++) acc2[o][h][pj] = bv;
    }

    auto compute = [&](int buf) {
#pragma unroll
        for (int cc=0; cc<CCH; cc++) {
            const float* inrow = s_in + buf*IN_E + cc*ROWS*64;
            if (KS == 3) {
#pragma unroll
                for (int r=0; r<4; r++) {
                    const float* rw = inrow + r*64;
                    float e0 = rw[(tx==0) ? 0 : (px0-1)];
                    if (tx == 0) e0 = 0.f;
                    float4 m = *(const float4*)(rw + px0);
                    float e5 = rw[(tx==15) ? 63 : (px0+4)];
                    if (tx == 15) e5 = 0.f;
                    u64 a[6] = {pk(e0), pk(m.x), pk(m.y), pk(m.z), pk(m.w), pk(e5)};
#pragma unroll
                    for (int o=0; o<2; o++) {
                        const int dy = r - o;
                        if (dy < 0 || dy > 2) continue;
#pragma unroll
                        for (int dx=0; dx<3; dx++) {
                            const u64* wp = (const u64*)(s_w + buf*W_E
                                              + (cc*9 + dy*3 + dx)*TILE_D + 4*ty);
                            u64 w01 = wp[0], w23 = wp[1];
#pragma unroll
                            for (int pj=0; pj<4; pj++) {
                                fma2(acc2[o][0][pj], a[dx+pj], w01);
                                fma2(acc2[o][1][pj], a[dx+pj], w23);
                            }
                        }
                    }
                }
            } else {
                const u64* wp = (const u64*)(s_w + buf*W_E + cc*TILE_D + 4*ty);
                u64 w01 = wp[0], w23 = wp[1];
#pragma unroll
                for (int r=0; r<2; r++) {
                    float4 m = *(const float4*)(inrow + r*64 + px0);
                    u64 a4[4] = {pk(m.x), pk(m.y), pk(m.z), pk(m.w)};
#pragma unroll
                    for (int pj=0; pj<4; pj++) {
                        fma2(acc2[r][0][pj], a4[pj], w01);
                        fma2(acc2[r][1][pj], a4[pj], w23);
                    }
                }
            }
        }
    };

    constexpr int NCH = CIN/CCH;
    fill(0, 0);
    cp_commit();
    for (int ch = 0; ch < NCH; ch++) {
        cp_wait<0>();
        __syncthreads();
        if (ch+1 < NCH) {
            fill(ch+1, (ch+1) & 1);
            cp_commit();
        }
        compute(ch & 1);
    }

#pragma unroll
    for (int o=0; o<2; o++) {
        float acc[4][4];
#pragma unroll
        for (int h=0; h<2; h++)
#pragma unroll
            for (int pj=0; pj<4; pj++) {
                float2 f = up2(acc2[o][h][pj]);
                acc[2*h][pj] = f.x; acc[2*h+1][pj] = f.y;
            }
        const int y = y0 + o;
        if (OUTMODE == 1) {
#pragma unroll
            for (int dj=0; dj<4; dj++) {
                *(float4*)&out[((long)z*COUT + d0+dj)*HW + y*WW + px0]
                    = make_float4(acc[dj][0], acc[dj][1], acc[dj][2], acc[dj][3]);
            }
        } else if (OUTMODE == 2) {
#pragma unroll
            for (int dj=0; dj<4; dj++) {
                long idx = ((long)z*COUT + d0+dj)*HW + y*WW + px0;
                float4 rr = *(const float4*)&resid[idx];
                *(float4*)&out[idx] = make_float4(acc[dj][0]+rr.x, acc[dj][1]+rr.y,
                                                  acc[dj][2]+rr.z, acc[dj][3]+rr.w);
            }
        } else {  // OUTMODE 3: qkv
#pragma unroll
            for (int pj=0; pj<4; pj++) {
                float4 ov = make_float4(acc[0][pj], acc[1][pj], acc[2][pj], acc[3][pj]);
                *(float4*)&out[((long)z*HW + y*WW + px0 + pj)*288 + d0] = ov;
            }
            if (d0 < 192) {
                uint32_t* oh = (d0 < 96) ? o_qh : o_kh;
                uint32_t* ol = (d0 < 96) ? o_ql : o_kl;
                int c = (d0 < 96) ? d0 : (d0 - 96);
#pragma unroll
                for (int pj=0; pj<4; pj++) {
                    float a0 = acc[0][pj], a1 = acc[1][pj], a2 = acc[2][pj], a3 = acc[3][pj];
                    float h0 = bf_hi(a0), h1 = bf_hi(a1), h2 = bf_hi(a2), h3 = bf_hi(a3);
                    long base = ((long)(z*3 + (c>>5))*HW + (y*WW + px0 + pj))*16 + ((c & 31) >> 1);
                    *(uint2*)&oh[base] = make_uint2(bfpack(h0, h1), bfpack(h2, h3));
                    *(uint2*)&ol[base] = make_uint2(bfpack(a0-h0, a1-h1), bfpack(a2-h2, a3-h3));
                }
            }
        }
    }
}

// ---------------- generic 3xBF16 HMMA implicit-GEMM 3x3 conv, NST-stage pipeline ----------------
// m16n8k16 bf16 MMAs; smem bf16-pair u32, stride 20 (conflict-free).
// Block tile 128(M) x NTL*16(N), 8 warps = 4M x 2N, 2 blocks/SM.
// OUTM: 0 = channel-last fp32 (+bias); 1 = fp32 tile-32 (+bias, TWOIN selects buf);
//       2 = lrelu(+bias) then bf16 hi/lo split pair-tiles.
template<int NOUT, int NTL, int OUTM, bool TWOIN, int NST>
__global__ void __launch_bounds__(256, 2)
hmma_conv(const uint32_t* __restrict__ aA_hi, const uint32_t* __restrict__ aA_lo,
          const uint32_t* __restrict__ aB_hi, const uint32_t* __restrict__ aB_lo,
          const uint32_t* __restrict__ w1_hi, const uint32_t* __restrict__ w1_lo,
          const uint32_t* __restrict__ w2_hi, const uint32_t* __restrict__ w2_lo,
          const float* __restrict__ bias,
          float* __restrict__ outf, float* __restrict__ outf2,
          uint32_t* __restrict__ outu, uint32_t* __restrict__ outul)
{
    constexpr int AST = 20;                 // u32 per row (16 pairs + pad)
    constexpr int A_E = 128*AST;            // 2560 u32 per buffer
    constexpr int BROWS = NTL*16;
    constexpr int B_E = BROWS*AST;
    extern __shared__ uint32_t smu[];
    uint32_t* sAh = smu;
    uint32_t* sAl = smu + NST*A_E;
    uint32_t* sBh = smu + 2*NST*A_E;
    uint32_t* sBl = smu + 2*NST*A_E + NST*B_E;

    const int tid = threadIdx.x;
    const int wid = tid >> 5, lane = tid & 31;
    const int z   = blockIdx.z;
    const int p0  = blockIdx.x * 128;
    const int n0  = blockIdx.y * BROWS;
    const int wm  = (wid & 3) * 32;
    const int wn  = (wid >> 2) * (NTL*8);
    const int gq  = lane >> 2;
    const int tg  = lane & 3;

    const uint32_t* a_hi = aA_hi; const uint32_t* a_lo = aA_lo;
    const uint32_t* b_hi = w1_hi; const uint32_t* b_lo = w1_lo;
    int f = z;
    if (TWOIN && z >= 12) {
        a_hi = aB_hi; a_lo = aB_lo; b_hi = w2_hi; b_lo = w2_lo; f = z - 12;
    }

    const uint32_t sAh_b = (uint32_t)__cvta_generic_to_shared(sAh);
    const uint32_t sAl_b = (uint32_t)__cvta_generic_to_shared(sAl);
    const uint32_t sBh_b = (uint32_t)__cvta_generic_to_shared(sBh);
    const uint32_t sBl_b = (uint32_t)__cvta_generic_to_shared(sBl);

    auto fillA = [&](int kc, int buf) {
        int tap = kc/3, cb = kc - tap*3;
        int dy = tap/3 - 1, dx = tap - (tap/3)*3 - 1;
        long cboff = ((long)(f*3 + cb))*HW*16;
        const uint32_t* ah = a_hi + cboff;
        const uint32_t* al = a_lo + cboff;
#pragma unroll
        for (int e = tid; e < 512; e += 256) {
            int m = e >> 2, seg = e & 3;
            int py = ((p0+m) >> 6) + dy;
            int px = ((p0+m) & 63) + dx;
            bool v = (py >= 0 && py < 64 && px >= 0 && px < 64);
            int pyc = min(max(py,0),63), pxc = min(max(px,0),63);
            long so = ((long)(pyc*64 + pxc))*16 + seg*4;
            uint32_t doff = (buf*A_E + m*AST + seg*4)*4u;
            cpa16(sAh_b + doff, ah + so, v);
            cpa16(sAl_b + doff, al + so, v);
        }
    };
    auto fillB = [&](int kc, int buf) {
#pragma unroll
        for (int e = tid; e < BROWS*4; e += 256) {
            int n = e >> 2, seg = e & 3;
            int ng = n0 + n;
            bool v = (ng < NOUT);
            int ns = v ? ng : 0;
            long so = (long)ns*432 + kc*16 + seg*4;
            uint32_t doff = (buf*B_E + n*AST + seg*4)*4u;
            cpa16(sBh_b + doff, b_hi + so, v);
            cpa16(sBl_b + doff, b_lo + so, v);
        }
    };

    float d[2][NTL][4];
#pragma unroll
    for (int mt=0; mt<2; mt++)
#pragma unroll
        for (int nt=0; nt<NTL; nt++)
#pragma unroll
            for (int r=0; r<4; r++) d[mt][nt][r] = 0.f;

    // NST-stage prologue: fills for chunks 0..NST-2 in flight
#pragma unroll
    for (int s = 0; s < NST-1; s++) {
        fillA(s, s); fillB(s, s); cp_commit();
    }

    for (int ch = 0; ch < 27; ch++) {
        cp_wait<NST-2>();        // fill(ch) complete (uniform 1 group/iter)
        __syncthreads();         // publish fill(ch); fence compute before overwrite
        if (ch+NST-1 < 27) {
            fillA(ch+NST-1, (ch+NST-1) % NST);
            fillB(ch+NST-1, (ch+NST-1) % NST);
        }
        cp_commit();             // unconditional: uniform group accounting
        const int buf = ch % NST;
        const uint32_t* Ah = sAh + buf*A_E;
        const uint32_t* Al = sAl + buf*A_E;
        const uint32_t* Bh = sBh + buf*B_E;
        const uint32_t* Bl = sBl + buf*B_E;
#pragma unroll
        for (int s=0; s<2; s++) {
            const int kp = s*8;              // pair offset within chunk
            uint32_t ah[2][4], al[2][4];
#pragma unroll
            for (int mt=0; mt<2; mt++) {
                int r = wm + mt*16 + gq;
                ah[mt][0] = Ah[r*AST + kp + tg];
                ah[mt][1] = Ah[(r+8)*AST + kp + tg];
                ah[mt][2] = Ah[r*AST + kp + 4 + tg];
                ah[mt][3] = Ah[(r+8)*AST + kp + 4 + tg];
                al[mt][0] = Al[r*AST + kp + tg];
                al[mt][1] = Al[(r+8)*AST + kp + tg];
                al[mt][2] = Al[r*AST + kp + 4 + tg];
                al[mt][3] = Al[(r+8)*AST + kp + 4 + tg];
            }
#pragma unroll
            for (int nt=0; nt<NTL; nt++) {
                int n = wn + nt*8 + gq;
                uint32_t bh0 = Bh[n*AST + kp + tg];
                uint32_t bh1 = Bh[n*AST + kp + 4 + tg];
                uint32_t bl0 = Bl[n*AST + kp + tg];
                uint32_t bl1 = Bl[n*AST + kp + 4 + tg];
                mma_bf16(d[0][nt], ah[0], bh0, bh1);
                mma_bf16(d[1][nt], ah[1], bh0, bh1);
                mma_bf16(d[0][nt], al[0], bh0, bh1);
                mma_bf16(d[1][nt], al[1], bh0, bh1);
                mma_bf16(d[0][nt], ah[0], bl0, bl1);
                mma_bf16(d[1][nt], ah[1], bl0, bl1);
            }
        }
    }

    // epilogue
    if (OUTM == 0) {
#pragma unroll
        for (int mt=0; mt<2; mt++) {
            int row = p0 + wm + mt*16 + gq;
            float* op0 = outf + ((long)z*HW + row)*NOUT;
            float* op1 = op0 + 8L*NOUT;
#pragma unroll
            for (int nt=0; nt<NTL; nt++) {
                int col = n0 + wn + nt*8 + tg*2;
                if (col < NOUT) {
                    float bx = __ldg(bias + col), by = __ldg(bias + col + 1);
                    *(float2*)(op0 + col) = make_float2(d[mt][nt][0] + bx, d[mt][nt][1] + by);
                    *(float2*)(op1 + col) = make_float2(d[mt][nt][2] + bx, d[mt][nt][3] + by);
                }
            }
        }
    } else if (OUTM == 1) {
        float* o = (TWOIN && z >= 12) ? outf2 : outf;
#pragma unroll
        for (int mt=0; mt<2; mt++) {
            int row = p0 + wm + mt*16 + gq;
#pragma unroll
            for (int nt=0; nt<NTL; nt++) {
                int col = n0 + wn + nt*8 + tg*2;
                if (col < NOUT) {
                    float bx = __ldg(bias + col), by = __ldg(bias + col + 1);
                    long b0i = ((long)(f*3 + (col>>5))*HW + row)*32 + (col & 31);
                    *(float2*)(o + b0i)        = make_float2(d[mt][nt][0] + bx, d[mt][nt][1] + by);
                    *(float2*)(o + b0i + 8*32) = make_float2(d[mt][nt][2] + bx, d[mt][nt][3] + by);
                }
            }
        }
    } else {  // OUTM == 2: lrelu + bf16 hi/lo split pair tiles
#pragma unroll
        for (int mt=0; mt<2; mt++) {
            int row = p0 + wm + mt*16 + gq;
#pragma unroll
            for (int nt=0; nt<NTL; nt++) {
                int col = n0 + wn + nt*8 + tg*2;
                if (col < NOUT) {
                    float bx = __ldg(bias + col), by = __ldg(bias + col + 1);
                    float v0 = d[mt][nt][0] + bx; v0 = (v0>=0.f)?v0:0.1f*v0;
                    float v1 = d[mt][nt][1] + by; v1 = (v1>=0.f)?v1:0.1f*v1;
                    float v2 = d[mt][nt][2] + bx; v2 = (v2>=0.f)?v2:0.1f*v2;
                    float v3 = d[mt][nt][3] + by; v3 = (v3>=0.f)?v3:0.1f*v3;
                    float h0 = bf_hi(v0), h1 = bf_hi(v1);
                    float h2 = bf_hi(v2), h3 = bf_hi(v3);
                    long b0i = ((long)(z*3 + (col>>5))*HW + row)*16 + ((col & 31) >> 1);
                    outu [b0i]        = bfpack(h0, h1);
                    outul[b0i]        = bfpack(v0-h0, v1-h1);
                    outu [b0i + 8*16] = bfpack(h2, h3);
                    outul[b0i + 8*16] = bfpack(v2-h2, v3-h3);
                }
            }
        }
    }
}

// ---------------- sum: off1 = lrelu(aq[jj]+ak[ii]+oc1_b), bf16 hi/lo pairs ----------------
__global__ void sum_k(const float* __restrict__ aq, const float* __restrict__ ak,
                      const float* __restrict__ bias,
                      uint32_t* __restrict__ oh, uint32_t* __restrict__ ol)
{
    long i = (long)blockIdx.x*256 + threadIdx.x;   // 4-channel groups
    const long TOT = 24L*3*4096*8;
    if (i >= TOT) return;
    int seg = (int)(i & 7);
    long r = i >> 3;
    int p = (int)(r & 4095); r >>= 12;
    int cb = (int)(r % 3);
    int img = (int)(r / 3);
    int pair = img >> 2, b = img & 3;
    int jj = pair >> 1, l = pair & 1;
    int ii = l ? ((jj==2) ? 1 : 2) : ((jj==0) ? 1 : 0);
    long qi = (((long)(b*3+jj)*3 + cb)*HW + p)*32 + seg*4;
    long ki = (((long)(b*3+ii)*3 + cb)*HW + p)*32 + seg*4;
    float4 a = *(const float4*)&aq[qi];
    float4 k = *(const float4*)&ak[ki];
    int c = cb*32 + seg*4;
    float t0 = a.x + k.x + bias[c+0]; t0 = (t0>=0.f)?t0:0.1f*t0;
    float t1 = a.y + k.y + bias[c+1]; t1 = (t1>=0.f)?t1:0.1f*t1;
    float t2 = a.z + k.z + bias[c+2]; t2 = (t2>=0.f)?t2:0.1f*t2;
    float t3 = a.w + k.w + bias[c+3]; t3 = (t3>=0.f)?t3:0.1f*t3;
    float h0 = bf_hi(t0), h1 = bf_hi(t1), h2 = bf_hi(t2), h3 = bf_hi(t3);
    long oidx = (((long)img*3 + cb)*HW + p)*16 + seg*2;
    *(uint2*)&oh[oidx] = make_uint2(bfpack(h0, h1), bfpack(h2, h3));
    *(uint2*)&ol[oidx] = make_uint2(bfpack(t0-h0, t1-h1), bfpack(t2-h2, t3-h3));
}

// ---------------- deformable top-2 attention ----------------
__global__ void __launch_bounds__(128) attn_k(
    const float* __restrict__ qkv,
    const float* __restrict__ om_all,
    float* __restrict__ w_all, float* __restrict__ v_all)
{
    __shared__ __align__(16) float4 s_wgt[4][72];
    __shared__ __align__(16) int4   s_off[4][72];
    const int warp = threadIdx.x >> 5;
    const int lane = threadIdx.x & 31;
    const int p = blockIdx.x*4 + warp;
    const int b = blockIdx.y;
    const int pair = blockIdx.z;
    const int jj = pair >> 1;
    const int l  = pair & 1;
    const int ii = l ? ((jj==2) ? 1 : 2) : ((jj==0) ? 1 : 0);
    const int y = p >> 6, x = p & 63;
    const float* ombase = om_all + ((pair*4 + b)*HW + (long)p)*216;

    for (int t = lane; t < 72; t += 32) {
        float oy = ombase[t];
        float ox = ombase[72 + t];
        float mm = ombase[144 + t];
        int n = t % 9;
        float m  = 1.f/(1.f + expf(-mm));
        float py = oy + (float)(n/3 - 1 + y);
        float px = ox + (float)(n%3 - 1 + x);
        float y0f = floorf(py), x0f = floorf(px);
        float wy = py - y0f, wx = px - x0f;
        int iy0 = (int)y0f, ix0 = (int)x0f;
        int iy1 = iy0 + 1, ix1 = ix0 + 1;
        float vy0 = (iy0 >= 0 && iy0 < HH) ? 1.f : 0.f;
        float vy1 = (iy1 >= 0 && iy1 < HH) ? 1.f : 0.f;
        float vx0 = (ix0 >= 0 && ix0 < WW) ? 1.f : 0.f;
        float vx1 = (ix1 >= 0 && ix1 < WW) ? 1.f : 0.f;
        int cy0 = min(max(iy0,0),HH-1), cy1 = min(max(iy1,0),HH-1);
        int cx0 = min(max(ix0,0),WW-1), cx1 = min(max(ix1,0),WW-1);
        float wy0 = 1.f - wy, wx0 = 1.f - wx;
        s_wgt[warp][t] = make_float4(m*wy0*wx0*vy0*vx0, m*wy0*wx *vy0*vx1,
                                     m*wy *wx0*vy1*vx0, m*wy *wx *vy1*vx1);
        s_off[warp][t] = make_int4((cy0*WW+cx0)*288, (cy0*WW+cx1)*288,
                                   (cy1*WW+cx0)*288, (cy1*WW+cx1)*288);
    }
    __syncwarp();

    const bool act = (lane < 24);
    const int g = lane / 3;
    const float* qp = qkv + (((b*3+jj)*HW + (long)p)*288);
    float4 qv = make_float4(0,0,0,0);
    if (act) qv = __ldg((const float4*)(qp + 4*lane));
    const float* kb = qkv + (b*3+ii)*(long)HW*288 + 96 + 4*lane;

    float rel[9];
#pragma unroll
    for (int n=0; n<9; n++) {
        float part = 0.f;
        if (act) {
            float4 W = s_wgt[warp][g*9+n];
            int4   O = s_off[warp][g*9+n];
            float4 k0 = __ldg((const float4*)(kb + O.x));
            float4 k1 = __ldg((const float4*)(kb + O.y));
            float4 k2 = __ldg((const float4*)(kb + O.z));
            float4 k3 = __ldg((const float4*)(kb + O.w));
            float sx = W.x*k0.x + W.y*k1.x + W.z*k2.x + W.w*k3.x;
            float sy = W.x*k0.y + W.y*k1.y + W.z*k2.y + W.w*k3.y;
            float sz = W.x*k0.z + W.y*k1.z + W.z*k2.z + W.w*k3.z;
            float sw = W.x*k0.w + W.y*k1.w + W.z*k2.w + W.w*k3.w;
            part = sx*qv.x + sy*qv.y + sz*qv.z + sw*qv.w;
        }
#pragma unroll
        for (int o=16; o>0; o>>=1) part += __shfl_xor_sync(0xffffffffu, part, o);
        rel[n] = part;
    }

    float b1 = rel[0]; int i1 = 0; float b2 = -1e30f; int i2 = 0;
#pragma unroll
    for (int n=1; n<9; n++) {
        if (rel[n] > b1)      { b2 = b1; i2 = i1; b1 = rel[n]; i1 = n; }
        else if (rel[n] > b2) { b2 = rel[n]; i2 = n; }
    }
    float c1 = 1.f/(1.f + expf(b2 - b1));
    float c2 = 1.f - c1;
    if (lane == 0) w_all[(pair*4 + b)*HW + p] = c1*b1 + c2*b2;

    if (act) {
        const float* vb = kb + 96;
        float4 W1 = s_wgt[warp][g*9+i1]; int4 O1 = s_off[warp][g*9+i1];
        float4 W2 = s_wgt[warp][g*9+i2]; int4 O2 = s_off[warp][g*9+i2];
        float4 a0 = __ldg((const float4*)(vb + O1.x));
        float4 a1 = __ldg((const float4*)(vb + O1.y));
        float4 a2 = __ldg((const float4*)(vb + O1.z));
        float4 a3 = __ldg((const float4*)(vb + O1.w));
        float4 b0 = __ldg((const float4*)(vb + O2.x));
        float4 bb1= __ldg((const float4*)(vb + O2.y));
        float4 b2v= __ldg((const float4*)(vb + O2.z));
        float4 b3 = __ldg((const float4*)(vb + O2.w));
        float4 ov;
        ov.x = c1*(W1.x*a0.x + W1.y*a1.x + W1.z*a2.x + W1.w*a3.x)
             + c2*(W2.x*b0.x + W2.y*bb1.x + W2.z*b2v.x + W2.w*b3.x);
        ov.y = c1*(W1.x*a0.y + W1.y*a1.y + W1.z*a2.y + W1.w*a3.y)
             + c2*(W2.x*b0.y + W2.y*bb1.y + W2.z*b2v.y + W2.w*b3.y);
        ov.z = c1*(W1.x*a0.z + W1.y*a1.z + W1.z*a2.z + W1.w*a3.z)
             + c2*(W2.x*b0.z + W2.y*bb1.z + W2.z*b2v.z + W2.w*b3.z);
        ov.w = c1*(W1.x*a0.w + W1.y*a1.w + W1.z*a2.w + W1.w*a3.w)
             + c2*(W2.x*b0.w + W2.y*bb1.w + W2.z*b2v.w + W2.w*b3.w);
        *(float4*)(v_all + ((pair*4 + b)*HW + (long)p)*96 + 4*lane) = ov;
    }
}

// ---------------- fuse with smem transpose ----------------
__global__ void __launch_bounds__(384) fuse_k2(const float* __restrict__ w_all,
                                               const float* __restrict__ v_all,
                                               float* __restrict__ f)
{
    __shared__ float s[96][33];
    const int t = threadIdx.x;
    const int p0 = blockIdx.x*32;
    const int img = blockIdx.y;
    const int jj = img % 3, b = img / 3;
    const int z0 = (jj*2)*4 + b, z1 = (jj*2+1)*4 + b;
#pragma unroll
    for (int k=0; k<8; k++) {
        int e = t + k*384;
        int c = e % 96, pp = e / 96;
        int p = p0 + pp;
        float w0 = w_all[z0*HW + p];
        float w1 = w_all[z1*HW + p];
        float mx = fmaxf(w0, w1);
        float e0 = expf(w0-mx), e1 = expf(w1-mx);
        float inv = 1.f/(e0+e1);
        float v0 = v_all[((long)z0*HW + p)*96 + c];
        float v1 = v_all[((long)z1*HW + p)*96 + c];
        s[c][pp] = (e0*v0 + e1*v1)*inv;
    }
    __syncthreads();
#pragma unroll
    for (int k=0; k<8; k++) {
        int e = t + k*384;
        int pp = e % 32, c = e / 32;
        f[((long)img*96 + c)*HW + p0 + pp] = s[c][pp];
    }
}

// ---------------- host ----------------
static void* symaddr(const void* s) {
    void* p = nullptr;
    cudaGetSymbolAddress(&p, s);
    return p;
}

extern "C" void kernel_launch(void* const* d_in, const int* in_sizes, int n_in,
                              void* d_out, int out_size)
{
    const float* fea   = (const float*)d_in[0];
    const float* cf_w  = (const float*)d_in[1];
    const float* cf_b  = (const float*)d_in[2];
    const float* wq    = (const float*)d_in[3];
    const float* bq    = (const float*)d_in[4];
    const float* wk    = (const float*)d_in[5];
    const float* bk    = (const float*)d_in[6];
    const float* wv    = (const float*)d_in[7];
    const float* bv    = (const float*)d_in[8];
    const float* oc1_w = (const float*)d_in[9];
    const float* oc1_b = (const float*)d_in[10];
    const float* oc2_w = (const float*)d_in[11];
    const float* oc2_b = (const float*)d_in[12];
    const float* om_w  = (const float*)d_in[13];
    const float* om_b  = (const float*)d_in[14];
    const float* cl_w  = (const float*)d_in[15];
    const float* cl_b  = (const float*)d_in[16];
    float* out = (float*)d_out;

    float*    emb   = (float*)symaddr(g_emb);
    float*    qkv   = (float*)symaddr(g_qkv);
    uint32_t* q32h  = (uint32_t*)symaddr(g_q32h);
    uint32_t* q32l  = (uint32_t*)symaddr(g_q32l);
    uint32_t* k32h  = (uint32_t*)symaddr(g_k32h);
    uint32_t* k32l  = (uint32_t*)symaddr(g_k32l);
    float*    aq32  = (float*)symaddr(g_aq32);
    float*    ak32  = (float*)symaddr(g_ak32);
    uint32_t* off1h = (uint32_t*)symaddr(g_off1h);
    uint32_t* off1l = (uint32_t*)symaddr(g_off1l);
    uint32_t* off2h = (uint32_t*)symaddr(g_off2h);
    uint32_t* off2l = (uint32_t*)symaddr(g_off2l);
    float*    omb   = (float*)symaddr(g_om);
    float*    wall  = (float*)symaddr(g_wall);
    float*    vall  = (float*)symaddr(g_vall);
    float*    fbuf  = (float*)symaddr(g_f);
    float*    cfwt  = (float*)symaddr(g_cfwt);
    float*    qkvwt = (float*)symaddr(g_qkvwt);
    float*    qkvb  = (float*)symaddr(g_qkvb);
    uint32_t* oc1qh = (uint32_t*)symaddr(g_oc1qh);
    uint32_t* oc1ql = (uint32_t*)symaddr(g_oc1ql);
    uint32_t* oc1kh = (uint32_t*)symaddr(g_oc1kh);
    uint32_t* oc1kl = (uint32_t*)symaddr(g_oc1kl);
    uint32_t* oc2h  = (uint32_t*)symaddr(g_oc2h);
    uint32_t* oc2l  = (uint32_t*)symaddr(g_oc2l);
    uint32_t* omwth = (uint32_t*)symaddr(g_omwth);
    uint32_t* omwtl = (uint32_t*)symaddr(g_omwtl);
    float*    clwt  = (float*)symaddr(g_clwt);
    float*    zero  = (float*)symaddr(g_zero);

    const int SM48_3 = 2*(8*4*64 + 8*9*48)*4;      // 44032
    const int SM48_1 = 2*(8*2*64 + 8*1*48)*4;      // 11264
    const int SM32_3 = 2*(8*4*64 + 8*9*32)*4;      // 34816
    const int SM_BF6 = 3*(2560 + 1920)*2*4;        // 107520 (oc1/oc2, 3 stages)
    const int SM_BF7 = 2*(2560 + 2240)*2*4;        // 76800  (om, 2 stages)

    static bool attr_done = false;
    if (!attr_done) {
        cudaFuncSetAttribute((const void*)hmma_conv<216,7,0,false,2>,
                             cudaFuncAttributeMaxDynamicSharedMemorySize, SM_BF7);
        cudaFuncSetAttribute((const void*)hmma_conv<96,6,1,true,3>,
                             cudaFuncAttributeMaxDynamicSharedMemorySize, SM_BF6);
        cudaFuncSetAttribute((const void*)hmma_conv<96,6,2,false,3>,
                             cudaFuncAttributeMaxDynamicSharedMemorySize, SM_BF6);
        attr_done = true;
    }

    // 1) weight prep (bf16 hi/lo pair splits)
    prep_all<<<1319, 256>>>(cf_w, wq, wk, wv, bq, bk, bv, oc1_w, oc2_w, om_w, cl_w);

    // 2) emb = conv3x3(fea): NCHW -> NCHW (FFMA2, exact)
    conv2<64,96,48,3,8,1,5><<<dim3(2,32,12), dim3(16,12), SM48_3>>>(
        fea, cfwt, cf_b, emb, nullptr, nullptr, nullptr, nullptr, nullptr);

    // 3) qkv = 1x1(emb): chan-last 288 + q/k bf16 hi/lo pair tiles (FFMA2)
    conv2<96,288,48,1,8,3,5><<<dim3(6,32,12), dim3(16,12), SM48_1>>>(
        emb, qkvwt, qkvb, qkv, q32h, q32l, k32h, k32l, nullptr);

    // 4) oc1 via 3xBF16 HMMA (3-stage, 2 blk/SM): q-frames -> aq32, k -> ak32
    hmma_conv<96,6,1,true,3><<<dim3(32,1,24), 256, SM_BF6>>>(
        q32h, q32l, k32h, k32l, oc1qh, oc1ql, oc1kh, oc1kl, zero,
        aq32, ak32, nullptr, nullptr);

    // 5) off1 = lrelu(aq[jj]+ak[ii]+oc1_b), bf16 hi/lo pairs
    sum_k<<<9216, 256>>>(aq32, ak32, oc1_b, off1h, off1l);

    // 6) oc2 via 3xBF16 HMMA (3-stage, +lrelu, bf16 hi/lo out)
    hmma_conv<96,6,2,false,3><<<dim3(32,1,24), 256, SM_BF6>>>(
        off1h, off1l, nullptr, nullptr, oc2h, oc2l, nullptr, nullptr,
        oc2_b, nullptr, nullptr, off2h, off2l);

    // 7) om via 3xBF16 HMMA (2-stage, 2 blk/SM): channel-last 216 fp32
    hmma_conv<216,7,0,false,2><<<dim3(32,2,24), 256, SM_BF7>>>(
        off2h, off2l, nullptr, nullptr, omwth, omwtl, nullptr, nullptr,
        om_b, omb, nullptr, nullptr, nullptr);

    // 8) attention
    attn_k<<<dim3(1024,4,6), 128>>>(qkv, omb, wall, vall);

    // 9) fuse -> NCHW fbuf
    fuse_k2<<<dim3(128,12), 384>>>(wall, vall, fbuf);

    // 10) cl conv: NCHW -> NCHW out + residual (FFMA2)
    conv2<96,64,32,3,8,2,6><<<dim3(2,32,12), dim3(16,8), SM32_3>>>(
        fbuf, clwt, cl_b, out, nullptr, nullptr, nullptr, nullptr, fea);

    (void)in_sizes; (void)n_in; (void)out_size;
}

// round 17
// speedup vs baseline: 1.1475x; 1.1027x over previous
#include <cuda_runtime.h>
#include <math.h>
#include <stdint.h>

#define HW 4096
#define WW 64
#define HH 64

typedef unsigned long long u64;

// ---------------- packed f32x2 helpers ----------------
__device__ __forceinline__ u64 pk(float v) {
    u64 r; asm("mov.b64 %0, {%1, %1};" : "=l"(r) : "f"(v)); return r;
}
__device__ __forceinline__ u64 pk2(float a, float b) {
    u64 r; asm("mov.b64 %0, {%1, %2};" : "=l"(r) : "f"(a), "f"(b)); return r;
}
__device__ __forceinline__ void fma2(u64& d, u64 a, u64 b) {
    asm("fma.rn.f32x2 %0, %1, %2, %0;" : "+l"(d) : "l"(a), "l"(b));
}
__device__ __forceinline__ float2 up2(u64 v) {
    float2 f; asm("mov.b64 {%0, %1}, %2;" : "=f"(f.x), "=f"(f.y) : "l"(v)); return f;
}

// ---------------- cp.async helpers ----------------
__device__ __forceinline__ void cpa16(uint32_t dst, const void* src, bool v) {
    int sz = v ? 16 : 0;
    asm volatile("cp.async.ca.shared.global [%0], [%1], 16, %2;" :: "r"(dst), "l"(src), "r"(sz));
}
__device__ __forceinline__ void cp_commit() { asm volatile("cp.async.commit_group;"); }
template<int N> __device__ __forceinline__ void cp_wait() {
    asm volatile("cp.async.wait_group %0;" :: "n"(N));
}

// ---------------- bf16 helpers ----------------
__device__ __forceinline__ uint32_t bfpack(float e0, float e1) {
    uint32_t r; asm("cvt.rn.bf16x2.f32 %0, %1, %2;" : "=r"(r) : "f"(e1), "f"(e0));
    return r;
}
__device__ __forceinline__ float bf_hi(float x) {
    uint32_t u; asm("cvt.rn.bf16x2.f32 %0, %1, %1;" : "=r"(u) : "f"(x));
    return __uint_as_float(u << 16);
}
__device__ __forceinline__ void mma_bf16(float* d, const uint32_t* a,
                                         uint32_t b0, uint32_t b1) {
    asm volatile(
        "mma.sync.aligned.m16n8k16.row.col.f32.bf16.bf16.f32 "
        "{%0,%1,%2,%3}, {%4,%5,%6,%7}, {%8,%9}, {%0,%1,%2,%3};"
        : "+f"(d[0]), "+f"(d[1]), "+f"(d[2]), "+f"(d[3])
        : "r"(a[0]), "r"(a[1]), "r"(a[2]), "r"(a[3]), "r"(b0), "r"(b1));
}

// ---------------- device scratch ----------------
__device__ uint32_t g_feah[12L*2*HW*16];     // fea bf16-pair tiles hi
__device__ uint32_t g_feal[12L*2*HW*16];
__device__ float    g_emb [12L*96*HW];       // NCHW (qkv input)
__device__ float    g_qkv [12L*HW*288];      // channel-last (attn)
__device__ uint32_t g_q32h[12L*3*HW*16];
__device__ uint32_t g_q32l[12L*3*HW*16];
__device__ uint32_t g_k32h[12L*3*HW*16];
__device__ uint32_t g_k32l[12L*3*HW*16];
__device__ float    g_aq32[12L*3*HW*32];     // oc1(q) out, fp32 tile-32
__device__ float    g_ak32[12L*3*HW*32];
__device__ uint32_t g_off1h[24L*3*HW*16];
__device__ uint32_t g_off1l[24L*3*HW*16];
__device__ uint32_t g_off2h[24L*3*HW*16];
__device__ uint32_t g_off2l[24L*3*HW*16];
__device__ float    g_om  [24L*HW*216];
__device__ float    g_wall[24L*HW];
__device__ float    g_vall[24L*HW*96];
__device__ uint32_t g_fh  [12L*3*HW*16];     // fused feats bf16 tiles (cl input)
__device__ uint32_t g_fl  [12L*3*HW*16];
__device__ uint32_t g_embwh[96*288];         // emb weights bf16 pairs [cout][kc*16+pr]
__device__ uint32_t g_embwl[96*288];
__device__ float    g_qkvwt[96*288];
__device__ float    g_qkvb [288];
__device__ uint32_t g_oc1qh[96*432];
__device__ uint32_t g_oc1ql[96*432];
__device__ uint32_t g_oc1kh[96*432];
__device__ uint32_t g_oc1kl[96*432];
__device__ uint32_t g_oc2h [96*432];
__device__ uint32_t g_oc2l [96*432];
__device__ uint32_t g_omwth[216*432];
__device__ uint32_t g_omwtl[216*432];
__device__ uint32_t g_clwth[64*432];
__device__ uint32_t g_clwtl[64*432];
__device__ float    g_zero [256];

// ---------------- single prep kernel ----------------
__global__ void prep_all(const float* __restrict__ cf_w,
                         const float* __restrict__ wq, const float* __restrict__ wk,
                         const float* __restrict__ wv,
                         const float* __restrict__ bq, const float* __restrict__ bk,
                         const float* __restrict__ bv,
                         const float* __restrict__ oc1_w, const float* __restrict__ oc2_w,
                         const float* __restrict__ om_w,  const float* __restrict__ cl_w)
{
    int i = blockIdx.x*256 + threadIdx.x;
    if (i < 27648) {   // emb weights: [96][64*9] -> [96][288] pair tiles (CBLK=2)
        int d = i/288, r = i%288, kc = r>>4, pr = r&15;
        int tap = kc>>1, cb = kc&1;
        int cin0 = cb*32 + 2*pr;
        float w0 = cf_w[d*576 + cin0*9 + tap];
        float w1 = cf_w[d*576 + (cin0+1)*9 + tap];
        float h0 = bf_hi(w0), h1 = bf_hi(w1);
        g_embwh[i] = bfpack(h0, h1);
        g_embwl[i] = bfpack(w0-h0, w1-h1);
        return;
    }
    i -= 27648;
    if (i < 9216) {
        int d = i/96, c = i%96;
        g_qkvwt[c*288 + d]       = wq[i];
        g_qkvwt[c*288 + 96 + d]  = wk[i];
        g_qkvwt[c*288 + 192 + d] = wv[i];
        return;
    }
    i -= 9216;
    if (i < 96) { g_qkvb[i] = bq[i]; g_qkvb[96+i] = bk[i]; g_qkvb[192+i] = bv[i]; return; }
    i -= 96;
    if (i < 82944) {   // oc1
        int d = i/864, rem = i%864, cp = rem/9, tap = rem%9;
        int cin0 = 2*cp;
        float w0 = oc1_w[d*1728 + cin0*9 + tap];
        float w1 = oc1_w[d*1728 + (cin0+1)*9 + tap];
        float h0 = bf_hi(w0), h1 = bf_hi(w1);
        uint32_t hp = bfpack(h0, h1);
        uint32_t lp = bfpack(w0-h0, w1-h1);
        if (cin0 < 96) { int idx = d*432 + tap*48 + cp;      g_oc1qh[idx]=hp; g_oc1ql[idx]=lp; }
        else           { int idx = d*432 + tap*48 + (cp-48); g_oc1kh[idx]=hp; g_oc1kl[idx]=lp; }
        return;
    }
    i -= 82944;
    if (i < 41472) {   // oc2
        int d = i/432, rem = i%432, cp = rem/9, tap = rem%9;
        int cin0 = 2*cp;
        float w0 = oc2_w[d*864 + cin0*9 + tap];
        float w1 = oc2_w[d*864 + (cin0+1)*9 + tap];
        float h0 = bf_hi(w0), h1 = bf_hi(w1);
        int idx = d*432 + tap*48 + cp;
        g_oc2h[idx] = bfpack(h0, h1);
        g_oc2l[idx] = bfpack(w0-h0, w1-h1);
        return;
    }
    i -= 41472;
    if (i < 93312) {   // om
        int d = i/432, rem = i%432, cp = rem/9, tap = rem%9;
        int cin0 = 2*cp;
        float w0 = om_w[d*864 + cin0*9 + tap];
        float w1 = om_w[d*864 + (cin0+1)*9 + tap];
        float h0 = bf_hi(w0), h1 = bf_hi(w1);
        int idx = d*432 + tap*48 + cp;
        g_omwth[idx] = bfpack(h0, h1);
        g_omwtl[idx] = bfpack(w0-h0, w1-h1);
        return;
    }
    i -= 93312;
    if (i < 27648) {   // cl: [64][96*9] -> pair tiles
        int d = i/432, rem = i%432, cp = rem/9, tap = rem%9;
        int cin0 = 2*cp;
        float w0 = cl_w[d*864 + cin0*9 + tap];
        float w1 = cl_w[d*864 + (cin0+1)*9 + tap];
        float h0 = bf_hi(w0), h1 = bf_hi(w1);
        int idx = d*432 + tap*48 + cp;
        g_clwth[idx] = bfpack(h0, h1);
        g_clwtl[idx] = bfpack(w0-h0, w1-h1);
        return;
    }
}

// ---------------- split fea into bf16 hi/lo pair tiles ----------------
__global__ void __launch_bounds__(256) split_fea(const float* __restrict__ fea,
                                                 uint32_t* __restrict__ fh,
                                                 uint32_t* __restrict__ fl)
{
    int i = blockIdx.x*256 + threadIdx.x;    // 12*2*4096 threads
    int pix = i & 4095;
    int cb  = (i >> 12) & 1;
    int img = i >> 13;
    const float* src = fea + ((long)img*64 + cb*32)*HW + pix;
    uint32_t hbuf[16], lbuf[16];
#pragma unroll
    for (int pr = 0; pr < 16; pr++) {
        float w0 = src[(2*pr)*HW];
        float w1 = src[(2*pr+1)*HW];
        float h0 = bf_hi(w0), h1 = bf_hi(w1);
        hbuf[pr] = bfpack(h0, h1);
        lbuf[pr] = bfpack(w0-h0, w1-h1);
    }
    long o = ((long)(img*2 + cb)*HW + pix)*16;
#pragma unroll
    for (int q = 0; q < 4; q++) {
        *(uint4*)&fh[o + q*4] = *(uint4*)&hbuf[q*4];
        *(uint4*)&fl[o + q*4] = *(uint4*)&lbuf[q*4];
    }
}

// ---------------- conv2: FFMA2 conv (qkv only) ----------------
template<int CIN, int COUT, int TILE_D, int KS, int CCH, int MAXB>
__global__ void __launch_bounds__(16*(TILE_D/4), MAXB)
conv2(const float* __restrict__ inA,
      const float* __restrict__ wt, const float* __restrict__ bias,
      float* __restrict__ out, uint32_t* __restrict__ o_qh, uint32_t* __restrict__ o_ql,
      uint32_t* __restrict__ o_kh, uint32_t* __restrict__ o_kl)
{
    constexpr int NT   = 16*(TILE_D/4);
    constexpr int ROWS = 2;
    constexpr int IN_E = CCH*ROWS*64;
    constexpr int W_E  = CCH*TILE_D;
    extern __shared__ float sm[];
    float* s_in = sm;
    float* s_w  = sm + 2*IN_E;

    const int tx  = threadIdx.x, ty = threadIdx.y;
    const int tid = ty*16 + tx;
    const int y0  = 2*blockIdx.y;
    const int z   = blockIdx.z;
    const int dblk = blockIdx.x*TILE_D;
    const int d0  = dblk + 4*ty;
    const int px0 = 4*tx;

    const float* pin = inA + (long)z*CIN*HW;
    const uint32_t s_in_b = (uint32_t)__cvta_generic_to_shared(s_in);
    const uint32_t s_w_b  = (uint32_t)__cvta_generic_to_shared(s_w);

    auto fill = [&](int ch, int buf) {
        const float* cbase = pin + (long)ch*CCH*HW;
        for (int e = tid; e < CCH*ROWS*16; e += NT) {
            int q  = e & 15;
            int r  = (e >> 4) % ROWS;
            int cc = e / (16*ROWS);
            int yy = y0+r;
            const float* src = cbase + cc*HW + yy*WW + q*4;
            uint32_t dst = s_in_b + (buf*IN_E + (cc*ROWS + r)*64 + q*4)*4u;
            cpa16(dst, src, true);
        }
        const float* wbase = wt + ((long)ch*CCH)*COUT + dblk;
        for (int e = tid; e < W_E/4; e += NT) {
            int qd = e % (TILE_D/4);
            int t  = e / (TILE_D/4);
            const float* src = wbase + (long)t*COUT + qd*4;
            uint32_t dst = s_w_b + (buf*W_E + t*TILE_D + qd*4)*4u;
            cpa16(dst, src, true);
        }
    };

    u64 acc2[2][2][4];
#pragma unroll
    for (int h=0; h<2; h++) {
        u64 bv = pk2(bias[d0+2*h], bias[d0+2*h+1]);
#pragma unroll
        for (int o=0; o<2; o++)
#pragma unroll
            for (int pj=0; pj<4; pj++) acc2[o][h][pj] = bv;
    }

    auto compute = [&](int buf) {
#pragma unroll
        for (int cc=0; cc<CCH; cc++) {
            const float* inrow = s_in + buf*IN_E + cc*ROWS*64;
            const u64* wp = (const u64*)(s_w + buf*W_E + cc*TILE_D + 4*ty);
            u64 w01 = wp[0], w23 = wp[1];
#pragma unroll
            for (int r=0; r<2; r++) {
                float4 m = *(const float4*)(inrow + r*64 + px0);
                u64 a4[4] = {pk(m.x), pk(m.y), pk(m.z), pk(m.w)};
#pragma unroll
                for (int pj=0; pj<4; pj++) {
                    fma2(acc2[r][0][pj], a4[pj], w01);
                    fma2(acc2[r][1][pj], a4[pj], w23);
                }
            }
        }
    };

    constexpr int NCHL = CIN/CCH;
    fill(0, 0);
    cp_commit();
    for (int ch = 0; ch < NCHL; ch++) {
        cp_wait<0>();
        __syncthreads();
        if (ch+1 < NCHL) {
            fill(ch+1, (ch+1) & 1);
            cp_commit();
        }
        compute(ch & 1);
    }

#pragma unroll
    for (int o=0; o<2; o++) {
        float acc[4][4];
#pragma unroll
        for (int h=0; h<2; h++)
#pragma unroll
            for (int pj=0; pj<4; pj++) {
                float2 f = up2(acc2[o][h][pj]);
                acc[2*h][pj] = f.x; acc[2*h+1][pj] = f.y;
            }
        const int y = y0 + o;
#pragma unroll
        for (int pj=0; pj<4; pj++) {
            float4 ov = make_float4(acc[0][pj], acc[1][pj], acc[2][pj], acc[3][pj]);
            *(float4*)&out[((long)z*HW + y*WW + px0 + pj)*288 + d0] = ov;
        }
        if (d0 < 192) {
            uint32_t* oh = (d0 < 96) ? o_qh : o_kh;
            uint32_t* ol = (d0 < 96) ? o_ql : o_kl;
            int c = (d0 < 96) ? d0 : (d0 - 96);
#pragma unroll
            for (int pj=0; pj<4; pj++) {
                float a0 = acc[0][pj], a1 = acc[1][pj], a2 = acc[2][pj], a3 = acc[3][pj];
                float h0 = bf_hi(a0), h1 = bf_hi(a1), h2 = bf_hi(a2), h3 = bf_hi(a3);
                long base = ((long)(z*3 + (c>>5))*HW + (y*WW + px0 + pj))*16 + ((c & 31) >> 1);
                *(uint2*)&oh[base] = make_uint2(bfpack(h0, h1), bfpack(h2, h3));
                *(uint2*)&ol[base] = make_uint2(bfpack(a0-h0, a1-h1), bfpack(a2-h2, a3-h3));
            }
        }
    }
}

// ---------------- generic 3xBF16 HMMA implicit-GEMM 3x3 conv ----------------
// NCH = K chunks, CBLK = channel blocks per image in A tiles.
// OUTM: 0 chan-last fp32; 1 fp32 tile-32 (TWOIN buf select); 2 lrelu+bf16 hi/lo;
//       3 NCHW + resid; 4 NCHW.
template<int NOUT, int NTL, int OUTM, bool TWOIN, int NST, int NCH, int CBLK>
__global__ void __launch_bounds__(256, 2)
hmma_conv(const uint32_t* __restrict__ aA_hi, const uint32_t* __restrict__ aA_lo,
          const uint32_t* __restrict__ aB_hi, const uint32_t* __restrict__ aB_lo,
          const uint32_t* __restrict__ w1_hi, const uint32_t* __restrict__ w1_lo,
          const uint32_t* __restrict__ w2_hi, const uint32_t* __restrict__ w2_lo,
          const float* __restrict__ bias,
          float* __restrict__ outf, float* __restrict__ outf2,
          uint32_t* __restrict__ outu, uint32_t* __restrict__ outul,
          const float* __restrict__ resid)
{
    constexpr int AST = 20;
    constexpr int A_E = 128*AST;
    constexpr int BROWS = NTL*16;
    constexpr int B_E = BROWS*AST;
    constexpr int BKS = NCH*16;             // B row K-stride in u32
    extern __shared__ uint32_t smu[];
    uint32_t* sAh = smu;
    uint32_t* sAl = smu + NST*A_E;
    uint32_t* sBh = smu + 2*NST*A_E;
    uint32_t* sBl = smu + 2*NST*A_E + NST*B_E;

    const int tid = threadIdx.x;
    const int wid = tid >> 5, lane = tid & 31;
    const int z   = blockIdx.z;
    const int p0  = blockIdx.x * 128;
    const int n0  = blockIdx.y * BROWS;
    const int wm  = (wid & 3) * 32;
    const int wn  = (wid >> 2) * (NTL*8);
    const int gq  = lane >> 2;
    const int tg  = lane & 3;

    const uint32_t* a_hi = aA_hi; const uint32_t* a_lo = aA_lo;
    const uint32_t* b_hi = w1_hi; const uint32_t* b_lo = w1_lo;
    int f = z;
    if (TWOIN && z >= 12) {
        a_hi = aB_hi; a_lo = aB_lo; b_hi = w2_hi; b_lo = w2_lo; f = z - 12;
    }

    const uint32_t sAh_b = (uint32_t)__cvta_generic_to_shared(sAh);
    const uint32_t sAl_b = (uint32_t)__cvta_generic_to_shared(sAl);
    const uint32_t sBh_b = (uint32_t)__cvta_generic_to_shared(sBh);
    const uint32_t sBl_b = (uint32_t)__cvta_generic_to_shared(sBl);

    auto fillA = [&](int kc, int buf) {
        int tap = kc/CBLK, cb = kc - tap*CBLK;
        int dy = tap/3 - 1, dx = tap - (tap/3)*3 - 1;
        long cboff = ((long)(f*CBLK + cb))*HW*16;
        const uint32_t* ah = a_hi + cboff;
        const uint32_t* al = a_lo + cboff;
#pragma unroll
        for (int e = tid; e < 512; e += 256) {
            int m = e >> 2, seg = e & 3;
            int py = ((p0+m) >> 6) + dy;
            int px = ((p0+m) & 63) + dx;
            bool v = (py >= 0 && py < 64 && px >= 0 && px < 64);
            int pyc = min(max(py,0),63), pxc = min(max(px,0),63);
            long so = ((long)(pyc*64 + pxc))*16 + seg*4;
            uint32_t doff = (buf*A_E + m*AST + seg*4)*4u;
            cpa16(sAh_b + doff, ah + so, v);
            cpa16(sAl_b + doff, al + so, v);
        }
    };
    auto fillB = [&](int kc, int buf) {
#pragma unroll
        for (int e = tid; e < BROWS*4; e += 256) {
            int n = e >> 2, seg = e & 3;
            int ng = n0 + n;
            bool v = (ng < NOUT);
            int ns = v ? ng : 0;
            long so = (long)ns*BKS + kc*16 + seg*4;
            uint32_t doff = (buf*B_E + n*AST + seg*4)*4u;
            cpa16(sBh_b + doff, b_hi + so, v);
            cpa16(sBl_b + doff, b_lo + so, v);
        }
    };

    float d[2][NTL][4];
#pragma unroll
    for (int mt=0; mt<2; mt++)
#pragma unroll
        for (int nt=0; nt<NTL; nt++)
#pragma unroll
            for (int r=0; r<4; r++) d[mt][nt][r] = 0.f;

#pragma unroll
    for (int s = 0; s < NST-1; s++) {
        fillA(s, s); fillB(s, s); cp_commit();
    }

    for (int ch = 0; ch < NCH; ch++) {
        cp_wait<NST-2>();
        __syncthreads();
        if (ch+NST-1 < NCH) {
            fillA(ch+NST-1, (ch+NST-1) % NST);
            fillB(ch+NST-1, (ch+NST-1) % NST);
        }
        cp_commit();
        const int buf = ch % NST;
        const uint32_t* Ah = sAh + buf*A_E;
        const uint32_t* Al = sAl + buf*A_E;
        const uint32_t* Bh = sBh + buf*B_E;
        const uint32_t* Bl = sBl + buf*B_E;
#pragma unroll
        for (int s=0; s<2; s++) {
            const int kp = s*8;
            uint32_t ah[2][4], al[2][4];
#pragma unroll
            for (int mt=0; mt<2; mt++) {
                int r = wm + mt*16 + gq;
                ah[mt][0] = Ah[r*AST + kp + tg];
                ah[mt][1] = Ah[(r+8)*AST + kp + tg];
                ah[mt][2] = Ah[r*AST + kp + 4 + tg];
                ah[mt][3] = Ah[(r+8)*AST + kp + 4 + tg];
                al[mt][0] = Al[r*AST + kp + tg];
                al[mt][1] = Al[(r+8)*AST + kp + tg];
                al[mt][2] = Al[r*AST + kp + 4 + tg];
                al[mt][3] = Al[(r+8)*AST + kp + 4 + tg];
            }
#pragma unroll
            for (int nt=0; nt<NTL; nt++) {
                int n = wn + nt*8 + gq;
                uint32_t bh0 = Bh[n*AST + kp + tg];
                uint32_t bh1 = Bh[n*AST + kp + 4 + tg];
                uint32_t bl0 = Bl[n*AST + kp + tg];
                uint32_t bl1 = Bl[n*AST + kp + 4 + tg];
                mma_bf16(d[0][nt], ah[0], bh0, bh1);
                mma_bf16(d[1][nt], ah[1], bh0, bh1);
                mma_bf16(d[0][nt], al[0], bh0, bh1);
                mma_bf16(d[1][nt], al[1], bh0, bh1);
                mma_bf16(d[0][nt], ah[0], bl0, bl1);
                mma_bf16(d[1][nt], ah[1], bl0, bl1);
            }
        }
    }

    // epilogue
    if (OUTM == 0) {
#pragma unroll
        for (int mt=0; mt<2; mt++) {
            int row = p0 + wm + mt*16 + gq;
            float* op0 = outf + ((long)z*HW + row)*NOUT;
            float* op1 = op0 + 8L*NOUT;
#pragma unroll
            for (int nt=0; nt<NTL; nt++) {
                int col = n0 + wn + nt*8 + tg*2;
                if (col < NOUT) {
                    float bx = __ldg(bias + col), by = __ldg(bias + col + 1);
                    *(float2*)(op0 + col) = make_float2(d[mt][nt][0] + bx, d[mt][nt][1] + by);
                    *(float2*)(op1 + col) = make_float2(d[mt][nt][2] + bx, d[mt][nt][3] + by);
                }
            }
        }
    } else if (OUTM == 1) {
        float* o = (TWOIN && z >= 12) ? outf2 : outf;
#pragma unroll
        for (int mt=0; mt<2; mt++) {
            int row = p0 + wm + mt*16 + gq;
#pragma unroll
            for (int nt=0; nt<NTL; nt++) {
                int col = n0 + wn + nt*8 + tg*2;
                if (col < NOUT) {
                    float bx = __ldg(bias + col), by = __ldg(bias + col + 1);
                    long b0i = ((long)(f*3 + (col>>5))*HW + row)*32 + (col & 31);
                    *(float2*)(o + b0i)        = make_float2(d[mt][nt][0] + bx, d[mt][nt][1] + by);
                    *(float2*)(o + b0i + 8*32) = make_float2(d[mt][nt][2] + bx, d[mt][nt][3] + by);
                }
            }
        }
    } else if (OUTM == 2) {
#pragma unroll
        for (int mt=0; mt<2; mt++) {
            int row = p0 + wm + mt*16 + gq;
#pragma unroll
            for (int nt=0; nt<NTL; nt++) {
                int col = n0 + wn + nt*8 + tg*2;
                if (col < NOUT) {
                    float bx = __ldg(bias + col), by = __ldg(bias + col + 1);
                    float v0 = d[mt][nt][0] + bx; v0 = (v0>=0.f)?v0:0.1f*v0;
                    float v1 = d[mt][nt][1] + by; v1 = (v1>=0.f)?v1:0.1f*v1;
                    float v2 = d[mt][nt][2] + bx; v2 = (v2>=0.f)?v2:0.1f*v2;
                    float v3 = d[mt][nt][3] + by; v3 = (v3>=0.f)?v3:0.1f*v3;
                    float h0 = bf_hi(v0), h1 = bf_hi(v1);
                    float h2 = bf_hi(v2), h3 = bf_hi(v3);
                    long b0i = ((long)(z*3 + (col>>5))*HW + row)*16 + ((col & 31) >> 1);
                    outu [b0i]        = bfpack(h0, h1);
                    outul[b0i]        = bfpack(v0-h0, v1-h1);
                    outu [b0i + 8*16] = bfpack(h2, h3);
                    outul[b0i + 8*16] = bfpack(v2-h2, v3-h3);
                }
            }
        }
    } else {  // OUTM 3/4: NCHW (+resid for 3)
#pragma unroll
        for (int mt=0; mt<2; mt++) {
            int row = p0 + wm + mt*16 + gq;
#pragma unroll
            for (int nt=0; nt<NTL; nt++) {
                int col = n0 + wn + nt*8 + tg*2;
                if (col < NOUT) {
                    float bx = __ldg(bias + col), by = __ldg(bias + col + 1);
                    long i00 = ((long)z*NOUT + col)*HW + row;
                    long i10 = i00 + HW;
                    float r00=0.f, r02=0.f, r10=0.f, r12=0.f;
                    if (OUTM == 3) {
                        r00 = resid[i00]; r02 = resid[i00+8];
                        r10 = resid[i10]; r12 = resid[i10+8];
                    }
                    outf[i00]   = d[mt][nt][0] + bx + r00;
                    outf[i10]   = d[mt][nt][1] + by + r10;
                    outf[i00+8] = d[mt][nt][2] + bx + r02;
                    outf[i10+8] = d[mt][nt][3] + by + r12;
                }
            }
        }
    }
}

// ---------------- sum: off1 = lrelu(aq[jj]+ak[ii]+oc1_b), bf16 hi/lo pairs ----------------
__global__ void sum_k(const float* __restrict__ aq, const float* __restrict__ ak,
                      const float* __restrict__ bias,
                      uint32_t* __restrict__ oh, uint32_t* __restrict__ ol)
{
    long i = (long)blockIdx.x*256 + threadIdx.x;
    const long TOT = 24L*3*4096*8;
    if (i >= TOT) return;
    int seg = (int)(i & 7);
    long r = i >> 3;
    int p = (int)(r & 4095); r >>= 12;
    int cb = (int)(r % 3);
    int img = (int)(r / 3);
    int pair = img >> 2, b = img & 3;
    int jj = pair >> 1, l = pair & 1;
    int ii = l ? ((jj==2) ? 1 : 2) : ((jj==0) ? 1 : 0);
    long qi = (((long)(b*3+jj)*3 + cb)*HW + p)*32 + seg*4;
    long ki = (((long)(b*3+ii)*3 + cb)*HW + p)*32 + seg*4;
    float4 a = *(const float4*)&aq[qi];
    float4 k = *(const float4*)&ak[ki];
    int c = cb*32 + seg*4;
    float t0 = a.x + k.x + bias[c+0]; t0 = (t0>=0.f)?t0:0.1f*t0;
    float t1 = a.y + k.y + bias[c+1]; t1 = (t1>=0.f)?t1:0.1f*t1;
    float t2 = a.z + k.z + bias[c+2]; t2 = (t2>=0.f)?t2:0.1f*t2;
    float t3 = a.w + k.w + bias[c+3]; t3 = (t3>=0.f)?t3:0.1f*t3;
    float h0 = bf_hi(t0), h1 = bf_hi(t1), h2 = bf_hi(t2), h3 = bf_hi(t3);
    long oidx = (((long)img*3 + cb)*HW + p)*16 + seg*2;
    *(uint2*)&oh[oidx] = make_uint2(bfpack(h0, h1), bfpack(h2, h3));
    *(uint2*)&ol[oidx] = make_uint2(bfpack(t0-h0, t1-h1), bfpack(t2-h2, t3-h3));
}

// ---------------- deformable top-2 attention ----------------
__global__ void __launch_bounds__(128) attn_k(
    const float* __restrict__ qkv,
    const float* __restrict__ om_all,
    float* __restrict__ w_all, float* __restrict__ v_all)
{
    __shared__ __align__(16) float4 s_wgt[4][72];
    __shared__ __align__(16) int4   s_off[4][72];
    const int warp = threadIdx.x >> 5;
    const int lane = threadIdx.x & 31;
    const int p = blockIdx.x*4 + warp;
    const int b = blockIdx.y;
    const int pair = blockIdx.z;
    const int jj = pair >> 1;
    const int l  = pair & 1;
    const int ii = l ? ((jj==2) ? 1 : 2) : ((jj==0) ? 1 : 0);
    const int y = p >> 6, x = p & 63;
    const float* ombase = om_all + ((pair*4 + b)*HW + (long)p)*216;

    for (int t = lane; t < 72; t += 32) {
        float oy = ombase[t];
        float ox = ombase[72 + t];
        float mm = ombase[144 + t];
        int n = t % 9;
        float m  = 1.f/(1.f + expf(-mm));
        float py = oy + (float)(n/3 - 1 + y);
        float px = ox + (float)(n%3 - 1 + x);
        float y0f = floorf(py), x0f = floorf(px);
        float wy = py - y0f, wx = px - x0f;
        int iy0 = (int)y0f, ix0 = (int)x0f;
        int iy1 = iy0 + 1, ix1 = ix0 + 1;
        float vy0 = (iy0 >= 0 && iy0 < HH) ? 1.f : 0.f;
        float vy1 = (iy1 >= 0 && iy1 < HH) ? 1.f : 0.f;
        float vx0 = (ix0 >= 0 && ix0 < WW) ? 1.f : 0.f;
        float vx1 = (ix1 >= 0 && ix1 < WW) ? 1.f : 0.f;
        int cy0 = min(max(iy0,0),HH-1), cy1 = min(max(iy1,0),HH-1);
        int cx0 = min(max(ix0,0),WW-1), cx1 = min(max(ix1,0),WW-1);
        float wy0 = 1.f - wy, wx0 = 1.f - wx;
        s_wgt[warp][t] = make_float4(m*wy0*wx0*vy0*vx0, m*wy0*wx *vy0*vx1,
                                     m*wy *wx0*vy1*vx0, m*wy *wx *vy1*vx1);
        s_off[warp][t] = make_int4((cy0*WW+cx0)*288, (cy0*WW+cx1)*288,
                                   (cy1*WW+cx0)*288, (cy1*WW+cx1)*288);
    }
    __syncwarp();

    const bool act = (lane < 24);
    const int g = lane / 3;
    const float* qp = qkv + (((b*3+jj)*HW + (long)p)*288);
    float4 qv = make_float4(0,0,0,0);
    if (act) qv = __ldg((const float4*)(qp + 4*lane));
    const float* kb = qkv + (b*3+ii)*(long)HW*288 + 96 + 4*lane;

    float rel[9];
#pragma unroll
    for (int n=0; n<9; n++) {
        float part = 0.f;
        if (act) {
            float4 W = s_wgt[warp][g*9+n];
            int4   O = s_off[warp][g*9+n];
            float4 k0 = __ldg((const float4*)(kb + O.x));
            float4 k1 = __ldg((const float4*)(kb + O.y));
            float4 k2 = __ldg((const float4*)(kb + O.z));
            float4 k3 = __ldg((const float4*)(kb + O.w));
            float sx = W.x*k0.x + W.y*k1.x + W.z*k2.x + W.w*k3.x;
            float sy = W.x*k0.y + W.y*k1.y + W.z*k2.y + W.w*k3.y;
            float sz = W.x*k0.z + W.y*k1.z + W.z*k2.z + W.w*k3.z;
            float sw = W.x*k0.w + W.y*k1.w + W.z*k2.w + W.w*k3.w;
            part = sx*qv.x + sy*qv.y + sz*qv.z + sw*qv.w;
        }
#pragma unroll
        for (int o=16; o>0; o>>=1) part += __shfl_xor_sync(0xffffffffu, part, o);
        rel[n] = part;
    }

    float b1 = rel[0]; int i1 = 0; float b2 = -1e30f; int i2 = 0;
#pragma unroll
    for (int n=1; n<9; n++) {
        if (rel[n] > b1)      { b2 = b1; i2 = i1; b1 = rel[n]; i1 = n; }
        else if (rel[n] > b2) { b2 = rel[n]; i2 = n; }
    }
    float c1 = 1.f/(1.f + expf(b2 - b1));
    float c2 = 1.f - c1;
    if (lane == 0) w_all[(pair*4 + b)*HW + p] = c1*b1 + c2*b2;

    if (act) {
        const float* vb = kb + 96;
        float4 W1 = s_wgt[warp][g*9+i1]; int4 O1 = s_off[warp][g*9+i1];
        float4 W2 = s_wgt[warp][g*9+i2]; int4 O2 = s_off[warp][g*9+i2];
        float4 a0 = __ldg((const float4*)(vb + O1.x));
        float4 a1 = __ldg((const float4*)(vb + O1.y));
        float4 a2 = __ldg((const float4*)(vb + O1.z));
        float4 a3 = __ldg((const float4*)(vb + O1.w));
        float4 b0 = __ldg((const float4*)(vb + O2.x));
        float4 bb1= __ldg((const float4*)(vb + O2.y));
        float4 b2v= __ldg((const float4*)(vb + O2.z));
        float4 b3 = __ldg((const float4*)(vb + O2.w));
        float4 ov;
        ov.x = c1*(W1.x*a0.x + W1.y*a1.x + W1.z*a2.x + W1.w*a3.x)
             + c2*(W2.x*b0.x + W2.y*bb1.x + W2.z*b2v.x + W2.w*b3.x);
        ov.y = c1*(W1.x*a0.y + W1.y*a1.y + W1.z*a2.y + W1.w*a3.y)
             + c2*(W2.x*b0.y + W2.y*bb1.y + W2.z*b2v.y + W2.w*b3.y);
        ov.z = c1*(W1.x*a0.z + W1.y*a1.z + W1.z*a2.z + W1.w*a3.z)
             + c2*(W2.x*b0.z + W2.y*bb1.z + W2.z*b2v.z + W2.w*b3.z);
        ov.w = c1*(W1.x*a0.w + W1.y*a1.w + W1.z*a2.w + W1.w*a3.w)
             + c2*(W2.x*b0.w + W2.y*bb1.w + W2.z*b2v.w + W2.w*b3.w);
        *(float4*)(v_all + ((pair*4 + b)*HW + (long)p)*96 + 4*lane) = ov;
    }
}

// ---------------- fuse: softmax combine -> bf16 hi/lo pair tiles ----------------
__global__ void __launch_bounds__(384) fuse_k2(const float* __restrict__ w_all,
                                               const float* __restrict__ v_all,
                                               uint32_t* __restrict__ fh,
                                               uint32_t* __restrict__ fl)
{
    __shared__ float s[96][33];
    const int t = threadIdx.x;
    const int p0 = blockIdx.x*32;
    const int img = blockIdx.y;
    const int jj = img % 3, b = img / 3;
    const int z0 = (jj*2)*4 + b, z1 = (jj*2+1)*4 + b;
#pragma unroll
    for (int k=0; k<8; k++) {
        int e = t + k*384;
        int c = e % 96, pp = e / 96;
        int p = p0 + pp;
        float w0 = w_all[z0*HW + p];
        float w1 = w_all[z1*HW + p];
        float mx = fmaxf(w0, w1);
        float e0 = expf(w0-mx), e1 = expf(w1-mx);
        float inv = 1.f/(e0+e1);
        float v0 = v_all[((long)z0*HW + p)*96 + c];
        float v1 = v_all[((long)z1*HW + p)*96 + c];
        s[c][pp] = (e0*v0 + e1*v1)*inv;
    }
    __syncthreads();
#pragma unroll
    for (int k=0; k<4; k++) {
        int e = t + k*384;
        int pp = e & 31, cpi = e >> 5;     // cpi 0..47
        int c = 2*cpi;
        float v0 = s[c][pp], v1 = s[c+1][pp];
        float h0 = bf_hi(v0), h1 = bf_hi(v1);
        long o = (((long)img*3 + (c>>5))*HW + p0 + pp)*16 + ((c & 31) >> 1);
        fh[o] = bfpack(h0, h1);
        fl[o] = bfpack(v0-h0, v1-h1);
    }
}

// ---------------- host ----------------
static void* symaddr(const void* s) {
    void* p = nullptr;
    cudaGetSymbolAddress(&p, s);
    return p;
}

extern "C" void kernel_launch(void* const* d_in, const int* in_sizes, int n_in,
                              void* d_out, int out_size)
{
    const float* fea   = (const float*)d_in[0];
    const float* cf_w  = (const float*)d_in[1];
    const float* cf_b  = (const float*)d_in[2];
    const float* wq    = (const float*)d_in[3];
    const float* bq    = (const float*)d_in[4];
    const float* wk    = (const float*)d_in[5];
    const float* bk    = (const float*)d_in[6];
    const float* wv    = (const float*)d_in[7];
    const float* bv    = (const float*)d_in[8];
    const float* oc1_w = (const float*)d_in[9];
    const float* oc1_b = (const float*)d_in[10];
    const float* oc2_w = (const float*)d_in[11];
    const float* oc2_b = (const float*)d_in[12];
    const float* om_w  = (const float*)d_in[13];
    const float* om_b  = (const float*)d_in[14];
    const float* cl_w  = (const float*)d_in[15];
    const float* cl_b  = (const float*)d_in[16];
    float* out = (float*)d_out;

    uint32_t* feah  = (uint32_t*)symaddr(g_feah);
    uint32_t* feal  = (uint32_t*)symaddr(g_feal);
    float*    emb   = (float*)symaddr(g_emb);
    float*    qkv   = (float*)symaddr(g_qkv);
    uint32_t* q32h  = (uint32_t*)symaddr(g_q32h);
    uint32_t* q32l  = (uint32_t*)symaddr(g_q32l);
    uint32_t* k32h  = (uint32_t*)symaddr(g_k32h);
    uint32_t* k32l  = (uint32_t*)symaddr(g_k32l);
    float*    aq32  = (float*)symaddr(g_aq32);
    float*    ak32  = (float*)symaddr(g_ak32);
    uint32_t* off1h = (uint32_t*)symaddr(g_off1h);
    uint32_t* off1l = (uint32_t*)symaddr(g_off1l);
    uint32_t* off2h = (uint32_t*)symaddr(g_off2h);
    uint32_t* off2l = (uint32_t*)symaddr(g_off2l);
    float*    omb   = (float*)symaddr(g_om);
    float*    wall  = (float*)symaddr(g_wall);
    float*    vall  = (float*)symaddr(g_vall);
    uint32_t* fh    = (uint32_t*)symaddr(g_fh);
    uint32_t* fl    = (uint32_t*)symaddr(g_fl);
    uint32_t* embwh = (uint32_t*)symaddr(g_embwh);
    uint32_t* embwl = (uint32_t*)symaddr(g_embwl);
    float*    qkvwt = (float*)symaddr(g_qkvwt);
    float*    qkvb  = (float*)symaddr(g_qkvb);
    uint32_t* oc1qh = (uint32_t*)symaddr(g_oc1qh);
    uint32_t* oc1ql = (uint32_t*)symaddr(g_oc1ql);
    uint32_t* oc1kh = (uint32_t*)symaddr(g_oc1kh);
    uint32_t* oc1kl = (uint32_t*)symaddr(g_oc1kl);
    uint32_t* oc2h  = (uint32_t*)symaddr(g_oc2h);
    uint32_t* oc2l  = (uint32_t*)symaddr(g_oc2l);
    uint32_t* omwth = (uint32_t*)symaddr(g_omwth);
    uint32_t* omwtl = (uint32_t*)symaddr(g_omwtl);
    uint32_t* clwth = (uint32_t*)symaddr(g_clwth);
    uint32_t* clwtl = (uint32_t*)symaddr(g_clwtl);
    float*    zero  = (float*)symaddr(g_zero);

    const int SM48_1  = 2*(8*2*64 + 8*1*48)*4;       // 11264 (qkv)
    const int SM_BF6  = 2*(2560 + 1920)*2*4;         // 71680 (oc1/oc2/emb)
    const int SM_BF7  = 2*(2560 + 2240)*2*4;         // 76800 (om)
    const int SM_BF4  = 2*(2560 + 1280)*2*4;         // 61440 (cl)

    static bool attr_done = false;
    if (!attr_done) {
        cudaFuncSetAttribute((const void*)hmma_conv<216,7,0,false,2,27,3>,
                             cudaFuncAttributeMaxDynamicSharedMemorySize, SM_BF7);
        cudaFuncSetAttribute((const void*)hmma_conv<96,6,1,true,2,27,3>,
                             cudaFuncAttributeMaxDynamicSharedMemorySize, SM_BF6);
        cudaFuncSetAttribute((const void*)hmma_conv<96,6,2,false,2,27,3>,
                             cudaFuncAttributeMaxDynamicSharedMemorySize, SM_BF6);
        cudaFuncSetAttribute((const void*)hmma_conv<96,6,4,false,2,18,2>,
                             cudaFuncAttributeMaxDynamicSharedMemorySize, SM_BF6);
        cudaFuncSetAttribute((const void*)hmma_conv<64,4,3,false,2,27,3>,
                             cudaFuncAttributeMaxDynamicSharedMemorySize, SM_BF4);
        attr_done = true;
    }

    // 1) weight prep (bf16 hi/lo splits for all hmma layers)
    prep_all<<<1103, 256>>>(cf_w, wq, wk, wv, bq, bk, bv, oc1_w, oc2_w, om_w, cl_w);

    // 2) split fea into bf16 hi/lo tiles
    split_fea<<<384, 256>>>(fea, feah, feal);

    // 3) emb = conv3x3(fea) via 3xBF16 HMMA -> NCHW
    hmma_conv<96,6,4,false,2,18,2><<<dim3(32,1,12), 256, SM_BF6>>>(
        feah, feal, nullptr, nullptr, embwh, embwl, nullptr, nullptr,
        cf_b, emb, nullptr, nullptr, nullptr, nullptr);

    // 4) qkv = 1x1(emb): chan-last 288 + q/k bf16 hi/lo pair tiles (FFMA2)
    conv2<96,288,48,1,8,5><<<dim3(6,32,12), dim3(16,12), SM48_1>>>(
        emb, qkvwt, qkvb, qkv, q32h, q32l, k32h, k32l);

    // 5) oc1 via 3xBF16 HMMA: q-frames (z<12) -> aq32, k -> ak32
    hmma_conv<96,6,1,true,2,27,3><<<dim3(32,1,24), 256, SM_BF6>>>(
        q32h, q32l, k32h, k32l, oc1qh, oc1ql, oc1kh, oc1kl, zero,
        aq32, ak32, nullptr, nullptr, nullptr);

    // 6) off1 = lrelu(aq[jj]+ak[ii]+oc1_b)
    sum_k<<<9216, 256>>>(aq32, ak32, oc1_b, off1h, off1l);

    // 7) oc2 via 3xBF16 HMMA (+lrelu, bf16 hi/lo out)
    hmma_conv<96,6,2,false,2,27,3><<<dim3(32,1,24), 256, SM_BF6>>>(
        off1h, off1l, nullptr, nullptr, oc2h, oc2l, nullptr, nullptr,
        oc2_b, nullptr, nullptr, off2h, off2l, nullptr);

    // 8) om via 3xBF16 HMMA: channel-last 216 fp32
    hmma_conv<216,7,0,false,2,27,3><<<dim3(32,2,24), 256, SM_BF7>>>(
        off2h, off2l, nullptr, nullptr, omwth, omwtl, nullptr, nullptr,
        om_b, omb, nullptr, nullptr, nullptr, nullptr);

    // 9) attention
    attn_k<<<dim3(1024,4,6), 128>>>(qkv, omb, wall, vall);

    // 10) fuse -> bf16 hi/lo tiles
    fuse_k2<<<dim3(128,12), 384>>>(wall, vall, fh, fl);

    // 11) cl via 3xBF16 HMMA: NCHW out + residual
    hmma_conv<64,4,3,false,2,27,3><<<dim3(32,1,12), 256, SM_BF4>>>(
        fh, fl, nullptr, nullptr, clwth, clwtl, nullptr, nullptr,
        cl_b, out, nullptr, nullptr, nullptr, fea);

    (void)in_sizes; (void)n_in; (void)out_size;
}